// round 1
// baseline (speedup 1.0000x reference)
#include <cuda_runtime.h>
#include <mma.h>
#include <math.h>
#include <stdint.h>

using namespace nvcuda;

// ---------------- problem constants ----------------
#define D_LLM 4096
#define D_FF  11008
#define NB    8
#define SEQ   256
#define SP    128
#define NH    32
#define HD    128
#define MROWS (NB*SEQ)          // 2048
#define MTV   (NB*128)          // 1024 text+vision rows
#define EPSR  1e-5f

// ---------------- scratch (device globals; no allocation) ----------------
__device__ float g_h   [MROWS*D_LLM];
__device__ float g_x   [MROWS*D_LLM];
__device__ float g_q   [MROWS*D_LLM];
__device__ float g_k   [MROWS*D_LLM];
__device__ float g_v   [MROWS*D_LLM];
__device__ float g_o   [MROWS*D_LLM];
__device__ float g_att [NB*NH*SEQ*SEQ];
__device__ float g_gate[MROWS*D_FF];
__device__ float g_up  [MROWS*D_FF];
__device__ float g_tv  [MTV*768];
__device__ float g_pool[NB*D_LLM];
__device__ float g_y1  [NB*768];

// ---------------- block reductions ----------------
__device__ __forceinline__ float blockReduceSum(float v){
    __shared__ float sh[33];
    int lane = threadIdx.x & 31, w = threadIdx.x >> 5;
    #pragma unroll
    for (int o=16;o>0;o>>=1) v += __shfl_down_sync(0xffffffffu, v, o);
    if (lane==0) sh[w]=v;
    __syncthreads();
    if (threadIdx.x==0){
        float s = 0.f;
        int nw = (blockDim.x+31)>>5;
        for (int i=0;i<nw;i++) s += sh[i];
        sh[32]=s;
    }
    __syncthreads();
    float r = sh[32];
    __syncthreads();
    return r;
}

__device__ __forceinline__ float blockReduceMax(float v){
    __shared__ float sh[33];
    int lane = threadIdx.x & 31, w = threadIdx.x >> 5;
    #pragma unroll
    for (int o=16;o>0;o>>=1) v = fmaxf(v, __shfl_down_sync(0xffffffffu, v, o));
    if (lane==0) sh[w]=v;
    __syncthreads();
    if (threadIdx.x==0){
        float s = -3.0e38f;
        int nw = (blockDim.x+31)>>5;
        for (int i=0;i<nw;i++) s = fmaxf(s, sh[i]);
        sh[32]=s;
    }
    __syncthreads();
    float r = sh[32];
    __syncthreads();
    return r;
}

// ---------------- TF32 WMMA GEMM:  C[M,N] = A[M,K] @ B[K,N]  ----------------
// EPI: 0 = plain store
//      1 = +bias[n], output rows remapped  out_row = blockIdx.y*256 + 128 + (m - blockIdx.y*128)
//          (in_proj: each 128-row block maps to text+vision rows of batch blockIdx.y)
//      2 = += resid (residual add)
// Requires: M%128==0, N%128==0, K%32==0 (true for all call sites).
template<int EPI>
__global__ void __launch_bounds__(256)
gemm_tf32(const float* __restrict__ A, const float* __restrict__ B,
          float* __restrict__ C, const float* __restrict__ bias,
          const float* __restrict__ resid, int M, int N, int K)
{
    __shared__ float As[128][36];   // row-major A tile [m][k], pad to 36
    __shared__ float Bs[32][132];   // row-major B tile [k][n], pad to 132

    const int tid = threadIdx.x;
    const int wid = tid >> 5;
    const int wm  = wid >> 2;       // 0..1   (64 rows each)
    const int wn  = wid & 3;        // 0..3   (32 cols each)
    const int m0  = blockIdx.y * 128;
    const int n0  = blockIdx.x * 128;

    wmma::fragment<wmma::accumulator,16,16,8,float> acc[4][2];
    #pragma unroll
    for (int i=0;i<4;i++)
        #pragma unroll
        for (int j=0;j<2;j++) wmma::fill_fragment(acc[i][j], 0.0f);

    for (int k0=0;k0<K;k0+=32){
        #pragma unroll
        for (int it=0; it<4; it++){
            int qi = tid + it*256;
            int r  = qi >> 3, c = (qi & 7) << 2;                 // A: 8 float4 per row
            float4 va = *(const float4*)(A + (size_t)(m0+r)*K + k0 + c);
            As[r][c]=va.x; As[r][c+1]=va.y; As[r][c+2]=va.z; As[r][c+3]=va.w;
            int rb = qi >> 5, cb = (qi & 31) << 2;               // B: 32 float4 per row
            float4 vb = *(const float4*)(B + (size_t)(k0+rb)*N + n0 + cb);
            Bs[rb][cb]=vb.x; Bs[rb][cb+1]=vb.y; Bs[rb][cb+2]=vb.z; Bs[rb][cb+3]=vb.w;
        }
        __syncthreads();
        #pragma unroll
        for (int ks=0; ks<32; ks+=8){
            wmma::fragment<wmma::matrix_a,16,16,8,wmma::precision::tf32,wmma::row_major> af[4];
            wmma::fragment<wmma::matrix_b,16,16,8,wmma::precision::tf32,wmma::row_major> bf[2];
            #pragma unroll
            for (int i=0;i<4;i++){
                wmma::load_matrix_sync(af[i], &As[wm*64+i*16][ks], 36);
                #pragma unroll
                for (int t=0;t<af[i].num_elements;t++) af[i].x[t] = wmma::__float_to_tf32(af[i].x[t]);
            }
            #pragma unroll
            for (int j=0;j<2;j++){
                wmma::load_matrix_sync(bf[j], &Bs[ks][wn*32+j*16], 132);
                #pragma unroll
                for (int t=0;t<bf[j].num_elements;t++) bf[j].x[t] = wmma::__float_to_tf32(bf[j].x[t]);
            }
            #pragma unroll
            for (int i=0;i<4;i++)
                #pragma unroll
                for (int j=0;j<2;j++)
                    wmma::mma_sync(acc[i][j], af[i], bf[j], acc[i][j]);
        }
        __syncthreads();
    }

    const int om0 = (EPI==1) ? (blockIdx.y*256 + 128) : m0;

    if (EPI==1){
        // broadcast bias into a 16x132 smem tile (reuse As) and add via accumulator frags
        float* bs = &As[0][0];
        for (int c=tid; c<128; c+=256){
            float bv = bias[n0+c];
            #pragma unroll
            for (int r=0;r<16;r++) bs[r*132+c]=bv;
        }
        __syncthreads();
        #pragma unroll
        for (int j=0;j<2;j++){
            wmma::fragment<wmma::accumulator,16,16,8,float> bfr;
            wmma::load_matrix_sync(bfr, bs + wn*32 + j*16, 132, wmma::mem_row_major);
            #pragma unroll
            for (int i=0;i<4;i++)
                #pragma unroll
                for (int t=0;t<8;t++) acc[i][j].x[t]+=bfr.x[t];
        }
    }

    #pragma unroll
    for (int i=0;i<4;i++)
        #pragma unroll
        for (int j=0;j<2;j++){
            size_t coff = (size_t)(om0 + wm*64 + i*16)*N + n0 + wn*32 + j*16;
            if (EPI==2){
                wmma::fragment<wmma::accumulator,16,16,8,float> rf;
                wmma::load_matrix_sync(rf, resid + coff, N, wmma::mem_row_major);
                #pragma unroll
                for (int t=0;t<8;t++) acc[i][j].x[t]+=rf.x[t];
            }
            wmma::store_matrix_sync(C + coff, acc[i][j], N, wmma::mem_row_major);
        }
}

// ---------------- embedding assembly ----------------
__global__ void gather_embed(const int* __restrict__ ids, const float* __restrict__ table,
                             float* __restrict__ h)
{
    int b = blockIdx.x >> 7, s = blockIdx.x & 127;
    int id = ids[b*SP + s];
    const float4* src = (const float4*)(table + (size_t)id*D_LLM);
    float4* dst = (float4*)(h + (size_t)(b*SEQ + s)*D_LLM);
    #pragma unroll
    for (int it=0; it<4; it++) dst[threadIdx.x + it*256] = src[threadIdx.x + it*256];
}

__global__ void stage_tv(const float* __restrict__ text, const float* __restrict__ vision,
                         float* __restrict__ tv)
{
    int b = blockIdx.x >> 7, r = blockIdx.x & 127;
    const float* src = (r < 64) ? (text + (size_t)(b*64 + r)*768)
                                : (vision + (size_t)(b*64 + (r-64))*768);
    float* dst = tv + (size_t)blockIdx.x*768;
    #pragma unroll
    for (int it=0; it<3; it++) dst[threadIdx.x + it*256] = src[threadIdx.x + it*256];
}

// ---------------- rmsnorm ----------------
__global__ void rmsnorm_kernel(const float* __restrict__ in, const float* __restrict__ w,
                               float* __restrict__ out)
{
    int row = blockIdx.x;
    const float* p = in + (size_t)row*D_LLM;
    float ss = 0.f;
    for (int d=threadIdx.x; d<D_LLM; d+=256){ float vv = p[d]; ss += vv*vv; }
    float tot = blockReduceSum(ss);
    float r = rsqrtf(tot*(1.0f/D_LLM) + EPSR);
    float* q = out + (size_t)row*D_LLM;
    for (int d=threadIdx.x; d<D_LLM; d+=256) q[d] = p[d]*r*w[d];
}

// ---------------- rope (in-place, q & k) ----------------
__global__ void rope_kernel(float* __restrict__ q, float* __restrict__ k)
{
    int m = blockIdx.x;
    int s = m & (SEQ-1);
    float* qr = q + (size_t)m*D_LLM;
    float* kr = k + (size_t)m*D_LLM;
    for (int p = threadIdx.x; p < NH*64; p += 256){
        int hh = p >> 6, i = p & 63;
        float invf = powf(10000.f, -(float)i * (1.f/64.f));
        float ang = (float)s * invf;
        float c, sn; sincosf(ang, &sn, &c);
        int b0 = hh*HD + i;
        float x1 = qr[b0], x2 = qr[b0+64];
        qr[b0]    = x1*c - x2*sn;
        qr[b0+64] = x2*c + x1*sn;
        x1 = kr[b0]; x2 = kr[b0+64];
        kr[b0]    = x1*c - x2*sn;
        kr[b0+64] = x2*c + x1*sn;
    }
}

// ---------------- attention: scores (Q K^T * scale), per (b,h), 64x64 tiles ----------------
__global__ void __launch_bounds__(256)
attn_scores(const float* __restrict__ Q, const float* __restrict__ K, float* __restrict__ att)
{
    int bh = blockIdx.z;
    int b = bh >> 5, h = bh & 31;
    int i0 = blockIdx.y*64, j0 = blockIdx.x*64;
    if (j0 > i0) return;                 // fully-masked tile: softmax never reads it

    __shared__ float Qs[64][33], Ks[64][33];
    int tid = threadIdx.x;
    int ty = tid >> 4, tx = tid & 15;
    float acc[4][4];
    #pragma unroll
    for (int r=0;r<4;r++)
        #pragma unroll
        for (int c=0;c<4;c++) acc[r][c]=0.f;

    const float* Qb = Q + (size_t)(b*SEQ + i0)*D_LLM + h*HD;
    const float* Kb = K + (size_t)(b*SEQ + j0)*D_LLM + h*HD;

    for (int d0=0; d0<HD; d0+=32){
        #pragma unroll
        for (int it=0; it<2; it++){
            int qi = tid + it*256;
            int r = qi >> 3, c = (qi & 7) << 2;
            float4 va = *(const float4*)(Qb + (size_t)r*D_LLM + d0 + c);
            Qs[r][c]=va.x; Qs[r][c+1]=va.y; Qs[r][c+2]=va.z; Qs[r][c+3]=va.w;
            float4 vb = *(const float4*)(Kb + (size_t)r*D_LLM + d0 + c);
            Ks[r][c]=vb.x; Ks[r][c+1]=vb.y; Ks[r][c+2]=vb.z; Ks[r][c+3]=vb.w;
        }
        __syncthreads();
        #pragma unroll
        for (int kk=0;kk<32;kk++){
            float a[4], bb[4];
            #pragma unroll
            for (int r=0;r<4;r++) a[r]=Qs[ty*4+r][kk];
            #pragma unroll
            for (int c=0;c<4;c++) bb[c]=Ks[tx*4+c][kk];
            #pragma unroll
            for (int r=0;r<4;r++)
                #pragma unroll
                for (int c=0;c<4;c++) acc[r][c] += a[r]*bb[c];
        }
        __syncthreads();
    }
    const float scale = 0.08838834764831845f;   // 1/sqrt(128)
    float* out = att + ((size_t)bh*SEQ + i0)*SEQ + j0;
    #pragma unroll
    for (int r=0;r<4;r++)
        #pragma unroll
        for (int c=0;c<4;c++)
            out[(size_t)(ty*4+r)*SEQ + tx*4+c] = acc[r][c]*scale;
}

// ---------------- softmax with causal mask (writes 0 for masked) ----------------
__global__ void softmax_kernel(float* __restrict__ att)
{
    int row = blockIdx.x;            // bh*256 + i
    int i = row & (SEQ-1);
    int j = threadIdx.x;
    float* p = att + (size_t)row*SEQ;
    float v = (j <= i) ? p[j] : -3.0e38f;
    float mx = blockReduceMax(v);
    float e = (j <= i) ? __expf(v - mx) : 0.f;
    float s = blockReduceSum(e);
    p[j] = e / s;
}

// ---------------- attention: O = P V, per (b,h), 64(i) x 64(d) tiles ----------------
__global__ void __launch_bounds__(256)
attn_av(const float* __restrict__ att, const float* __restrict__ V, float* __restrict__ O)
{
    int bh = blockIdx.z;
    int b = bh >> 5, h = bh & 31;
    int i0 = blockIdx.y*64, d0 = blockIdx.x*64;

    __shared__ float Ps[64][33], Vs[32][65];
    int tid = threadIdx.x;
    int ty = tid >> 4, tx = tid & 15;
    float acc[4][4];
    #pragma unroll
    for (int r=0;r<4;r++)
        #pragma unroll
        for (int c=0;c<4;c++) acc[r][c]=0.f;

    const float* Pb = att + ((size_t)bh*SEQ + i0)*SEQ;
    const float* Vb = V + (size_t)(b*SEQ)*D_LLM + h*HD + d0;

    int jend = i0 + 64;                 // rows beyond causal bound hold zeros anyway
    for (int j0=0; j0<jend; j0+=32){
        #pragma unroll
        for (int it=0; it<2; it++){
            int qi = tid + it*256;
            int r = qi >> 3, c = (qi & 7) << 2;           // P tile: 64x32
            float4 va = *(const float4*)(Pb + (size_t)r*SEQ + j0 + c);
            Ps[r][c]=va.x; Ps[r][c+1]=va.y; Ps[r][c+2]=va.z; Ps[r][c+3]=va.w;
            int rv = qi >> 4, cv = (qi & 15) << 2;        // V tile: 32x64
            float4 vb = *(const float4*)(Vb + (size_t)(j0+rv)*D_LLM + cv);
            Vs[rv][cv]=vb.x; Vs[rv][cv+1]=vb.y; Vs[rv][cv+2]=vb.z; Vs[rv][cv+3]=vb.w;
        }
        __syncthreads();
        #pragma unroll
        for (int kk=0;kk<32;kk++){
            float a[4], bb[4];
            #pragma unroll
            for (int r=0;r<4;r++) a[r]=Ps[ty*4+r][kk];
            #pragma unroll
            for (int c=0;c<4;c++) bb[c]=Vs[kk][tx*4+c];
            #pragma unroll
            for (int r=0;r<4;r++)
                #pragma unroll
                for (int c=0;c<4;c++) acc[r][c] += a[r]*bb[c];
        }
        __syncthreads();
    }
    float* out = O + (size_t)(b*SEQ + i0)*D_LLM + h*HD + d0;
    #pragma unroll
    for (int r=0;r<4;r++)
        #pragma unroll
        for (int c=0;c<4;c++)
            out[(size_t)(ty*4+r)*D_LLM + tx*4+c] = acc[r][c];
}

// ---------------- silu(gate) * up, in place into gate ----------------
__global__ void silu_mul(float* __restrict__ g, const float* __restrict__ u)
{
    size_t idx = (size_t)blockIdx.x*256 + threadIdx.x;
    float gv = g[idx];
    g[idx] = gv / (1.f + __expf(-gv)) * u[idx];
}

// ---------------- mean pool over sequence ----------------
__global__ void pool_kernel(const float* __restrict__ x, float* __restrict__ pool)
{
    int b = blockIdx.y;
    int d = blockIdx.x*256 + threadIdx.x;
    float acc = 0.f;
    const float* p = x + (size_t)(b*SEQ)*D_LLM + d;
    for (int s=0; s<SEQ; s++) acc += p[(size_t)s*D_LLM];
    pool[b*D_LLM + d] = acc * (1.f/SEQ);
}

// ---------------- head ----------------
__global__ void head1_kernel(const float* __restrict__ pool, const float* __restrict__ W1,
                             const float* __restrict__ b1, float* __restrict__ y1)
{
    __shared__ float sp[D_LLM];
    int b = blockIdx.y;
    for (int kk=threadIdx.x; kk<D_LLM; kk+=256) sp[kk]=pool[b*D_LLM+kk];
    __syncthreads();
    int n = blockIdx.x*256 + threadIdx.x;
    float acc = b1[n];
    for (int kk=0; kk<D_LLM; kk++) acc += sp[kk]*W1[(size_t)kk*768 + n];
    y1[b*768 + n] = acc;
}

__global__ void head2_kernel(const float* __restrict__ y1, const float* __restrict__ W2,
                             const float* __restrict__ b2, float* __restrict__ out)
{
    int b = blockIdx.x;
    float acc = 0.f;
    for (int kk=threadIdx.x; kk<768; kk+=256) acc += y1[b*768+kk]*W2[kk];
    float tot = blockReduceSum(acc);
    if (threadIdx.x==0) out[b] = tot + b2[0];
}

// ---------------- host orchestration ----------------
extern "C" void kernel_launch(void* const* d_in, const int* in_sizes, int n_in,
                              void* d_out, int out_size)
{
    const float* text   = (const float*)d_in[0];
    const float* vision = (const float*)d_in[1];
    const int*   ids    = (const int*)  d_in[2];
    const float* in_W   = (const float*)d_in[3];
    const float* in_b   = (const float*)d_in[4];
    const float* table  = (const float*)d_in[5];
    const float* Wq     = (const float*)d_in[6];
    const float* Wk     = (const float*)d_in[7];
    const float* Wv     = (const float*)d_in[8];
    const float* Wo     = (const float*)d_in[9];
    const float* ln1    = (const float*)d_in[10];
    const float* ln2    = (const float*)d_in[11];
    const float* Wg     = (const float*)d_in[12];
    const float* Wu     = (const float*)d_in[13];
    const float* Wd     = (const float*)d_in[14];
    const float* fnw    = (const float*)d_in[15];
    const float* o1W    = (const float*)d_in[16];
    const float* o1b    = (const float*)d_in[17];
    const float* o2W    = (const float*)d_in[18];
    const float* o2b    = (const float*)d_in[19];
    float* out = (float*)d_out;

    float *h,*x,*q,*k,*v,*o,*att,*gate,*up,*tv,*pool,*y1;
    cudaGetSymbolAddress((void**)&h,    g_h);
    cudaGetSymbolAddress((void**)&x,    g_x);
    cudaGetSymbolAddress((void**)&q,    g_q);
    cudaGetSymbolAddress((void**)&k,    g_k);
    cudaGetSymbolAddress((void**)&v,    g_v);
    cudaGetSymbolAddress((void**)&o,    g_o);
    cudaGetSymbolAddress((void**)&att,  g_att);
    cudaGetSymbolAddress((void**)&gate, g_gate);
    cudaGetSymbolAddress((void**)&up,   g_up);
    cudaGetSymbolAddress((void**)&tv,   g_tv);
    cudaGetSymbolAddress((void**)&pool, g_pool);
    cudaGetSymbolAddress((void**)&y1,   g_y1);

    // --- embedding assembly: h[b, 0:128] = table[ids], h[b,128:256] = [text;vision] @ in_W + in_b
    gather_embed<<<NB*SP, 256>>>(ids, table, h);
    stage_tv<<<MTV, 256>>>(text, vision, tv);
    gemm_tf32<1><<<dim3(D_LLM/128, MTV/128), 256>>>(tv, in_W, h, in_b, nullptr, MTV, D_LLM, 768);

    for (int l=0; l<2; l++){
        const float* wq = Wq + (size_t)l*D_LLM*D_LLM;
        const float* wk = Wk + (size_t)l*D_LLM*D_LLM;
        const float* wv = Wv + (size_t)l*D_LLM*D_LLM;
        const float* wo = Wo + (size_t)l*D_LLM*D_LLM;
        const float* wg = Wg + (size_t)l*D_LLM*D_FF;
        const float* wu = Wu + (size_t)l*D_LLM*D_FF;
        const float* wd = Wd + (size_t)l*D_FF*D_LLM;
        const float* l1 = ln1 + (size_t)l*D_LLM;
        const float* l2 = ln2 + (size_t)l*D_LLM;

        rmsnorm_kernel<<<MROWS, 256>>>(h, l1, x);
        gemm_tf32<0><<<dim3(D_LLM/128, MROWS/128), 256>>>(x, wq, q, nullptr, nullptr, MROWS, D_LLM, D_LLM);
        gemm_tf32<0><<<dim3(D_LLM/128, MROWS/128), 256>>>(x, wk, k, nullptr, nullptr, MROWS, D_LLM, D_LLM);
        gemm_tf32<0><<<dim3(D_LLM/128, MROWS/128), 256>>>(x, wv, v, nullptr, nullptr, MROWS, D_LLM, D_LLM);
        rope_kernel<<<MROWS, 256>>>(q, k);
        attn_scores<<<dim3(SEQ/64, SEQ/64, NB*NH), 256>>>(q, k, att);
        softmax_kernel<<<NB*NH*SEQ, 256>>>(att);
        attn_av<<<dim3(HD/64, SEQ/64, NB*NH), 256>>>(att, v, o);
        gemm_tf32<2><<<dim3(D_LLM/128, MROWS/128), 256>>>(o, wo, h, nullptr, h, MROWS, D_LLM, D_LLM);

        rmsnorm_kernel<<<MROWS, 256>>>(h, l2, x);
        gemm_tf32<0><<<dim3(D_FF/128, MROWS/128), 256>>>(x, wg, gate, nullptr, nullptr, MROWS, D_FF, D_LLM);
        gemm_tf32<0><<<dim3(D_FF/128, MROWS/128), 256>>>(x, wu, up,   nullptr, nullptr, MROWS, D_FF, D_LLM);
        silu_mul<<<(MROWS*(size_t)D_FF)/256, 256>>>(gate, up);
        gemm_tf32<2><<<dim3(D_LLM/128, MROWS/128), 256>>>(gate, wd, h, nullptr, h, MROWS, D_LLM, D_FF);
    }

    rmsnorm_kernel<<<MROWS, 256>>>(h, fnw, x);
    pool_kernel<<<dim3(D_LLM/256, NB), 256>>>(x, pool);
    head1_kernel<<<dim3(768/256, NB), 256>>>(pool, o1W, o1b, y1);
    head2_kernel<<<NB, 256>>>(y1, o2W, o2b, out);
}

// round 3
// speedup vs baseline: 1.6653x; 1.6653x over previous
#include <cuda_runtime.h>
#include <mma.h>
#include <math.h>
#include <stdint.h>

using namespace nvcuda;

// ---------------- problem constants ----------------
#define D_LLM 4096
#define D_FF  11008
#define NB    8
#define SEQ   256
#define SP    128
#define NH    32
#define HD    128
#define MROWS (NB*SEQ)          // 2048
#define MTV   (NB*128)          // 1024 text+vision rows
#define EPSR  1e-5f

// ---------------- scratch (device globals; no allocation) ----------------
__device__ float g_h   [MROWS*D_LLM];
__device__ float g_x   [MROWS*D_LLM];
__device__ float g_q   [MROWS*D_LLM];
__device__ float g_k   [MROWS*D_LLM];
__device__ float g_v   [MROWS*D_LLM];
__device__ float g_o   [MROWS*D_LLM];
__device__ float g_att [NB*NH*SEQ*SEQ];
__device__ float g_gate[MROWS*D_FF];
__device__ float g_up  [MROWS*D_FF];
__device__ float g_tv  [MTV*768];
__device__ float g_pool[NB*D_LLM];
__device__ float g_y1  [NB*768];

// ---------------- cp.async helpers ----------------
__device__ __forceinline__ void cp_async16(void* smem_dst, const void* gmem_src){
    uint32_t s = (uint32_t)__cvta_generic_to_shared(smem_dst);
    asm volatile("cp.async.cg.shared.global [%0], [%1], 16;\n" :: "r"(s), "l"(gmem_src));
}
__device__ __forceinline__ void cp_commit(){
    asm volatile("cp.async.commit_group;\n" ::: "memory");
}
template<int N>
__device__ __forceinline__ void cp_wait(){
    asm volatile("cp.async.wait_group %0;\n" :: "n"(N) : "memory");
}

// ---------------- block reductions ----------------
__device__ __forceinline__ float blockReduceSum(float v){
    __shared__ float sh[33];
    int lane = threadIdx.x & 31, w = threadIdx.x >> 5;
    #pragma unroll
    for (int o=16;o>0;o>>=1) v += __shfl_down_sync(0xffffffffu, v, o);
    if (lane==0) sh[w]=v;
    __syncthreads();
    if (threadIdx.x==0){
        float s = 0.f;
        int nw = (blockDim.x+31)>>5;
        for (int i=0;i<nw;i++) s += sh[i];
        sh[32]=s;
    }
    __syncthreads();
    float r = sh[32];
    __syncthreads();
    return r;
}

__device__ __forceinline__ float blockReduceMax(float v){
    __shared__ float sh[33];
    int lane = threadIdx.x & 31, w = threadIdx.x >> 5;
    #pragma unroll
    for (int o=16;o>0;o>>=1) v = fmaxf(v, __shfl_down_sync(0xffffffffu, v, o));
    if (lane==0) sh[w]=v;
    __syncthreads();
    if (threadIdx.x==0){
        float s = -3.0e38f;
        int nw = (blockDim.x+31)>>5;
        for (int i=0;i<nw;i++) s = fmaxf(s, sh[i]);
        sh[32]=s;
    }
    __syncthreads();
    float r = sh[32];
    __syncthreads();
    return r;
}

// ---------------- TF32 WMMA GEMM, 4-stage cp.async pipeline ----------------
//   C[M,N] = A[M,K] @ B[K,N]
// EPI: 0 = plain store
//      1 = +bias[n], output rows remapped  out_row = blockIdx.y*256 + 128 + (m % 128)
//      2 = += resid (residual add)
// Requires: M%128==0, N%128==0, K%32==0, K/32 >= 4.
#define GEMM_STAGES 4
#define GEMM_AE (128*36)
#define GEMM_BE (32*132)
#define GEMM_SMEM (GEMM_STAGES*(GEMM_AE+GEMM_BE)*4)

template<int EPI>
__global__ void __launch_bounds__(256)
gemm_tf32(const float* __restrict__ A, const float* __restrict__ B,
          float* __restrict__ C, const float* __restrict__ bias,
          const float* __restrict__ resid, int M, int N, int K)
{
    extern __shared__ float sm[];
    float* As = sm;                          // [ST][128][36]
    float* Bs = sm + GEMM_STAGES*GEMM_AE;    // [ST][32][132]

    const int tid = threadIdx.x;
    const int wid = tid >> 5;
    const int wm  = wid >> 2;       // 0..1   (64 rows each)
    const int wn  = wid & 3;        // 0..3   (32 cols each)
    const int m0  = blockIdx.y * 128;
    const int n0  = blockIdx.x * 128;
    const int KT  = K >> 5;         // chunks of 32

    wmma::fragment<wmma::accumulator,16,16,8,float> acc[4][2];
    #pragma unroll
    for (int i=0;i<4;i++)
        #pragma unroll
        for (int j=0;j<2;j++) wmma::fill_fragment(acc[i][j], 0.0f);

    // per-thread load coords (8 x 16B per chunk)
    auto load_chunk = [&](int st, int kt){
        const int k0 = kt << 5;
        float* Ad = As + st*GEMM_AE;
        float* Bd = Bs + st*GEMM_BE;
        #pragma unroll
        for (int it=0; it<4; it++){
            int qi = tid + it*256;
            int r  = qi >> 3, c = (qi & 7) << 2;          // A: 128 rows x 8 chunks
            cp_async16(Ad + r*36 + c, A + (size_t)(m0+r)*K + k0 + c);
            int rb = qi >> 5, cb = (qi & 31) << 2;        // B: 32 rows x 32 chunks
            cp_async16(Bd + rb*132 + cb, B + (size_t)(k0+rb)*N + n0 + cb);
        }
    };

    auto compute = [&](int st){
        float* Ab = As + st*GEMM_AE;
        float* Bb = Bs + st*GEMM_BE;
        #pragma unroll
        for (int ks=0; ks<32; ks+=8){
            wmma::fragment<wmma::matrix_a,16,16,8,wmma::precision::tf32,wmma::row_major> af[4];
            wmma::fragment<wmma::matrix_b,16,16,8,wmma::precision::tf32,wmma::row_major> bf[2];
            #pragma unroll
            for (int i=0;i<4;i++){
                wmma::load_matrix_sync(af[i], Ab + (wm*64+i*16)*36 + ks, 36);
                #pragma unroll
                for (int t=0;t<af[i].num_elements;t++) af[i].x[t] = wmma::__float_to_tf32(af[i].x[t]);
            }
            #pragma unroll
            for (int j=0;j<2;j++){
                wmma::load_matrix_sync(bf[j], Bb + ks*132 + wn*32 + j*16, 132);
                #pragma unroll
                for (int t=0;t<bf[j].num_elements;t++) bf[j].x[t] = wmma::__float_to_tf32(bf[j].x[t]);
            }
            #pragma unroll
            for (int i=0;i<4;i++)
                #pragma unroll
                for (int j=0;j<2;j++)
                    wmma::mma_sync(acc[i][j], af[i], bf[j], acc[i][j]);
        }
    };

    // prologue: pre-issue STAGES-1 chunks
    #pragma unroll
    for (int s=0; s<GEMM_STAGES-1; s++){
        load_chunk(s, s);
        cp_commit();
    }

    for (int kt=0; kt<KT; kt++){
        cp_wait<GEMM_STAGES-2>();
        __syncthreads();
        compute(kt & (GEMM_STAGES-1));
        __syncthreads();
        int nc = kt + GEMM_STAGES - 1;
        if (nc < KT) load_chunk(nc & (GEMM_STAGES-1), nc);
        cp_commit();
    }
    cp_wait<0>();
    __syncthreads();

    const int om0 = (EPI==1) ? (blockIdx.y*256 + 128) : m0;

    if (EPI==1){
        // broadcast bias into a 16x132 smem tile and add via accumulator frags
        float* bs = sm;
        for (int c=tid; c<128; c+=256){
            float bv = bias[n0+c];
            #pragma unroll
            for (int r=0;r<16;r++) bs[r*132+c]=bv;
        }
        __syncthreads();
        #pragma unroll
        for (int j=0;j<2;j++){
            wmma::fragment<wmma::accumulator,16,16,8,float> bfr;
            wmma::load_matrix_sync(bfr, bs + wn*32 + j*16, 132, wmma::mem_row_major);
            #pragma unroll
            for (int i=0;i<4;i++)
                #pragma unroll
                for (int t=0;t<8;t++) acc[i][j].x[t]+=bfr.x[t];
        }
    }

    #pragma unroll
    for (int i=0;i<4;i++)
        #pragma unroll
        for (int j=0;j<2;j++){
            size_t coff = (size_t)(om0 + wm*64 + i*16)*N + n0 + wn*32 + j*16;
            if (EPI==2){
                wmma::fragment<wmma::accumulator,16,16,8,float> rf;
                wmma::load_matrix_sync(rf, resid + coff, N, wmma::mem_row_major);
                #pragma unroll
                for (int t=0;t<8;t++) acc[i][j].x[t]+=rf.x[t];
            }
            wmma::store_matrix_sync(C + coff, acc[i][j], N, wmma::mem_row_major);
        }
}

// ---------------- embedding assembly ----------------
__global__ void gather_embed(const int* __restrict__ ids, const float* __restrict__ table,
                             float* __restrict__ h)
{
    int b = blockIdx.x >> 7, s = blockIdx.x & 127;
    int id = ids[b*SP + s];
    const float4* src = (const float4*)(table + (size_t)id*D_LLM);
    float4* dst = (float4*)(h + (size_t)(b*SEQ + s)*D_LLM);
    #pragma unroll
    for (int it=0; it<4; it++) dst[threadIdx.x + it*256] = src[threadIdx.x + it*256];
}

__global__ void stage_tv(const float* __restrict__ text, const float* __restrict__ vision,
                         float* __restrict__ tv)
{
    int b = blockIdx.x >> 7, r = blockIdx.x & 127;
    const float* src = (r < 64) ? (text + (size_t)(b*64 + r)*768)
                                : (vision + (size_t)(b*64 + (r-64))*768);
    float* dst = tv + (size_t)blockIdx.x*768;
    #pragma unroll
    for (int it=0; it<3; it++) dst[threadIdx.x + it*256] = src[threadIdx.x + it*256];
}

// ---------------- rmsnorm ----------------
__global__ void rmsnorm_kernel(const float* __restrict__ in, const float* __restrict__ w,
                               float* __restrict__ out)
{
    int row = blockIdx.x;
    const float* p = in + (size_t)row*D_LLM;
    float ss = 0.f;
    for (int d=threadIdx.x; d<D_LLM; d+=256){ float vv = p[d]; ss += vv*vv; }
    float tot = blockReduceSum(ss);
    float r = rsqrtf(tot*(1.0f/D_LLM) + EPSR);
    float* q = out + (size_t)row*D_LLM;
    for (int d=threadIdx.x; d<D_LLM; d+=256) q[d] = p[d]*r*w[d];
}

// ---------------- rope (in-place, q & k) ----------------
__global__ void rope_kernel(float* __restrict__ q, float* __restrict__ k)
{
    int m = blockIdx.x;
    int s = m & (SEQ-1);
    float* qr = q + (size_t)m*D_LLM;
    float* kr = k + (size_t)m*D_LLM;
    for (int p = threadIdx.x; p < NH*64; p += 256){
        int hh = p >> 6, i = p & 63;
        float invf = powf(10000.f, -(float)i * (1.f/64.f));
        float ang = (float)s * invf;
        float c, sn; sincosf(ang, &sn, &c);
        int b0 = hh*HD + i;
        float x1 = qr[b0], x2 = qr[b0+64];
        qr[b0]    = x1*c - x2*sn;
        qr[b0+64] = x2*c + x1*sn;
        x1 = kr[b0]; x2 = kr[b0+64];
        kr[b0]    = x1*c - x2*sn;
        kr[b0+64] = x2*c + x1*sn;
    }
}

// ---------------- attention: scores (Q K^T * scale), per (b,h), 64x64 tiles ----------------
__global__ void __launch_bounds__(256)
attn_scores(const float* __restrict__ Q, const float* __restrict__ K, float* __restrict__ att)
{
    int bh = blockIdx.z;
    int b = bh >> 5, h = bh & 31;
    int i0 = blockIdx.y*64, j0 = blockIdx.x*64;
    if (j0 > i0) return;                 // fully-masked tile: softmax never reads it

    __shared__ float Qs[64][33], Ks[64][33];
    int tid = threadIdx.x;
    int ty = tid >> 4, tx = tid & 15;
    float acc[4][4];
    #pragma unroll
    for (int r=0;r<4;r++)
        #pragma unroll
        for (int c=0;c<4;c++) acc[r][c]=0.f;

    const float* Qb = Q + (size_t)(b*SEQ + i0)*D_LLM + h*HD;
    const float* Kb = K + (size_t)(b*SEQ + j0)*D_LLM + h*HD;

    for (int d0=0; d0<HD; d0+=32){
        #pragma unroll
        for (int it=0; it<2; it++){
            int qi = tid + it*256;
            int r = qi >> 3, c = (qi & 7) << 2;
            float4 va = *(const float4*)(Qb + (size_t)r*D_LLM + d0 + c);
            Qs[r][c]=va.x; Qs[r][c+1]=va.y; Qs[r][c+2]=va.z; Qs[r][c+3]=va.w;
            float4 vb = *(const float4*)(Kb + (size_t)r*D_LLM + d0 + c);
            Ks[r][c]=vb.x; Ks[r][c+1]=vb.y; Ks[r][c+2]=vb.z; Ks[r][c+3]=vb.w;
        }
        __syncthreads();
        #pragma unroll
        for (int kk=0;kk<32;kk++){
            float a[4], bb[4];
            #pragma unroll
            for (int r=0;r<4;r++) a[r]=Qs[ty*4+r][kk];
            #pragma unroll
            for (int c=0;c<4;c++) bb[c]=Ks[tx*4+c][kk];
            #pragma unroll
            for (int r=0;r<4;r++)
                #pragma unroll
                for (int c=0;c<4;c++) acc[r][c] += a[r]*bb[c];
        }
        __syncthreads();
    }
    const float scale = 0.08838834764831845f;   // 1/sqrt(128)
    float* out = att + ((size_t)bh*SEQ + i0)*SEQ + j0;
    #pragma unroll
    for (int r=0;r<4;r++)
        #pragma unroll
        for (int c=0;c<4;c++)
            out[(size_t)(ty*4+r)*SEQ + tx*4+c] = acc[r][c]*scale;
}

// ---------------- softmax with causal mask (writes 0 for masked) ----------------
__global__ void softmax_kernel(float* __restrict__ att)
{
    int row = blockIdx.x;            // bh*256 + i
    int i = row & (SEQ-1);
    int j = threadIdx.x;
    float* p = att + (size_t)row*SEQ;
    float v = (j <= i) ? p[j] : -3.0e38f;
    float mx = blockReduceMax(v);
    float e = (j <= i) ? __expf(v - mx) : 0.f;
    float s = blockReduceSum(e);
    p[j] = e / s;
}

// ---------------- attention: O = P V, per (b,h), 64(i) x 64(d) tiles ----------------
__global__ void __launch_bounds__(256)
attn_av(const float* __restrict__ att, const float* __restrict__ V, float* __restrict__ O)
{
    int bh = blockIdx.z;
    int b = bh >> 5, h = bh & 31;
    int i0 = blockIdx.y*64, d0 = blockIdx.x*64;

    __shared__ float Ps[64][33], Vs[32][65];
    int tid = threadIdx.x;
    int ty = tid >> 4, tx = tid & 15;
    float acc[4][4];
    #pragma unroll
    for (int r=0;r<4;r++)
        #pragma unroll
        for (int c=0;c<4;c++) acc[r][c]=0.f;

    const float* Pb = att + ((size_t)bh*SEQ + i0)*SEQ;
    const float* Vb = V + (size_t)(b*SEQ)*D_LLM + h*HD + d0;

    int jend = i0 + 64;                 // rows beyond causal bound hold zeros anyway
    for (int j0=0; j0<jend; j0+=32){
        #pragma unroll
        for (int it=0; it<2; it++){
            int qi = tid + it*256;
            int r = qi >> 3, c = (qi & 7) << 2;           // P tile: 64x32
            float4 va = *(const float4*)(Pb + (size_t)r*SEQ + j0 + c);
            Ps[r][c]=va.x; Ps[r][c+1]=va.y; Ps[r][c+2]=va.z; Ps[r][c+3]=va.w;
            int rv = qi >> 4, cv = (qi & 15) << 2;        // V tile: 32x64
            float4 vb = *(const float4*)(Vb + (size_t)(j0+rv)*D_LLM + cv);
            Vs[rv][cv]=vb.x; Vs[rv][cv+1]=vb.y; Vs[rv][cv+2]=vb.z; Vs[rv][cv+3]=vb.w;
        }
        __syncthreads();
        #pragma unroll
        for (int kk=0;kk<32;kk++){
            float a[4], bb[4];
            #pragma unroll
            for (int r=0;r<4;r++) a[r]=Ps[ty*4+r][kk];
            #pragma unroll
            for (int c=0;c<4;c++) bb[c]=Vs[kk][tx*4+c];
            #pragma unroll
            for (int r=0;r<4;r++)
                #pragma unroll
                for (int c=0;c<4;c++) acc[r][c] += a[r]*bb[c];
        }
        __syncthreads();
    }
    float* out = O + (size_t)(b*SEQ + i0)*D_LLM + h*HD + d0;
    #pragma unroll
    for (int r=0;r<4;r++)
        #pragma unroll
        for (int c=0;c<4;c++)
            out[(size_t)(ty*4+r)*D_LLM + tx*4+c] = acc[r][c];
}

// ---------------- silu(gate) * up, in place into gate ----------------
__global__ void silu_mul(float* __restrict__ g, const float* __restrict__ u)
{
    size_t idx = (size_t)blockIdx.x*256 + threadIdx.x;
    float gv = g[idx];
    g[idx] = gv / (1.f + __expf(-gv)) * u[idx];
}

// ---------------- mean pool over sequence ----------------
__global__ void pool_kernel(const float* __restrict__ x, float* __restrict__ pool)
{
    int b = blockIdx.y;
    int d = blockIdx.x*256 + threadIdx.x;
    float acc = 0.f;
    const float* p = x + (size_t)(b*SEQ)*D_LLM + d;
    for (int s=0; s<SEQ; s++) acc += p[(size_t)s*D_LLM];
    pool[b*D_LLM + d] = acc * (1.f/SEQ);
}

// ---------------- head ----------------
__global__ void head1_kernel(const float* __restrict__ pool, const float* __restrict__ W1,
                             const float* __restrict__ b1, float* __restrict__ y1)
{
    __shared__ float sp[D_LLM];
    int b = blockIdx.y;
    for (int kk=threadIdx.x; kk<D_LLM; kk+=256) sp[kk]=pool[b*D_LLM+kk];
    __syncthreads();
    int n = blockIdx.x*256 + threadIdx.x;
    float acc = b1[n];
    for (int kk=0; kk<D_LLM; kk++) acc += sp[kk]*W1[(size_t)kk*768 + n];
    y1[b*768 + n] = acc;
}

__global__ void head2_kernel(const float* __restrict__ y1, const float* __restrict__ W2,
                             const float* __restrict__ b2, float* __restrict__ out)
{
    int b = blockIdx.x;
    float acc = 0.f;
    for (int kk=threadIdx.x; kk<768; kk+=256) acc += y1[b*768+kk]*W2[kk];
    float tot = blockReduceSum(acc);
    if (threadIdx.x==0) out[b] = tot + b2[0];
}

// ---------------- host orchestration ----------------
extern "C" void kernel_launch(void* const* d_in, const int* in_sizes, int n_in,
                              void* d_out, int out_size)
{
    const float* text   = (const float*)d_in[0];
    const float* vision = (const float*)d_in[1];
    const int*   ids    = (const int*)  d_in[2];
    const float* in_W   = (const float*)d_in[3];
    const float* in_b   = (const float*)d_in[4];
    const float* table  = (const float*)d_in[5];
    const float* Wq     = (const float*)d_in[6];
    const float* Wk     = (const float*)d_in[7];
    const float* Wv     = (const float*)d_in[8];
    const float* Wo     = (const float*)d_in[9];
    const float* ln1    = (const float*)d_in[10];
    const float* ln2    = (const float*)d_in[11];
    const float* Wg     = (const float*)d_in[12];
    const float* Wu     = (const float*)d_in[13];
    const float* Wd     = (const float*)d_in[14];
    const float* fnw    = (const float*)d_in[15];
    const float* o1W    = (const float*)d_in[16];
    const float* o1b    = (const float*)d_in[17];
    const float* o2W    = (const float*)d_in[18];
    const float* o2b    = (const float*)d_in[19];
    float* out = (float*)d_out;

    float *h,*x,*q,*k,*v,*o,*att,*gate,*up,*tv,*pool,*y1;
    cudaGetSymbolAddress((void**)&h,    g_h);
    cudaGetSymbolAddress((void**)&x,    g_x);
    cudaGetSymbolAddress((void**)&q,    g_q);
    cudaGetSymbolAddress((void**)&k,    g_k);
    cudaGetSymbolAddress((void**)&v,    g_v);
    cudaGetSymbolAddress((void**)&o,    g_o);
    cudaGetSymbolAddress((void**)&att,  g_att);
    cudaGetSymbolAddress((void**)&gate, g_gate);
    cudaGetSymbolAddress((void**)&up,   g_up);
    cudaGetSymbolAddress((void**)&tv,   g_tv);
    cudaGetSymbolAddress((void**)&pool, g_pool);
    cudaGetSymbolAddress((void**)&y1,   g_y1);

    // dynamic smem opt-in for the 4-stage GEMM (141 KB)
    cudaFuncSetAttribute(gemm_tf32<0>, cudaFuncAttributeMaxDynamicSharedMemorySize, GEMM_SMEM);
    cudaFuncSetAttribute(gemm_tf32<1>, cudaFuncAttributeMaxDynamicSharedMemorySize, GEMM_SMEM);
    cudaFuncSetAttribute(gemm_tf32<2>, cudaFuncAttributeMaxDynamicSharedMemorySize, GEMM_SMEM);

    // --- embedding assembly: h[b, 0:128] = table[ids], h[b,128:256] = [text;vision] @ in_W + in_b
    gather_embed<<<NB*SP, 256>>>(ids, table, h);
    stage_tv<<<MTV, 256>>>(text, vision, tv);
    gemm_tf32<1><<<dim3(D_LLM/128, MTV/128), 256, GEMM_SMEM>>>(tv, in_W, h, in_b, nullptr, MTV, D_LLM, 768);

    for (int l=0; l<2; l++){
        const float* wq = Wq + (size_t)l*D_LLM*D_LLM;
        const float* wk = Wk + (size_t)l*D_LLM*D_LLM;
        const float* wv = Wv + (size_t)l*D_LLM*D_LLM;
        const float* wo = Wo + (size_t)l*D_LLM*D_LLM;
        const float* wg = Wg + (size_t)l*D_LLM*D_FF;
        const float* wu = Wu + (size_t)l*D_LLM*D_FF;
        const float* wd = Wd + (size_t)l*D_FF*D_LLM;
        const float* l1 = ln1 + (size_t)l*D_LLM;
        const float* l2 = ln2 + (size_t)l*D_LLM;

        rmsnorm_kernel<<<MROWS, 256>>>(h, l1, x);
        gemm_tf32<0><<<dim3(D_LLM/128, MROWS/128), 256, GEMM_SMEM>>>(x, wq, q, nullptr, nullptr, MROWS, D_LLM, D_LLM);
        gemm_tf32<0><<<dim3(D_LLM/128, MROWS/128), 256, GEMM_SMEM>>>(x, wk, k, nullptr, nullptr, MROWS, D_LLM, D_LLM);
        gemm_tf32<0><<<dim3(D_LLM/128, MROWS/128), 256, GEMM_SMEM>>>(x, wv, v, nullptr, nullptr, MROWS, D_LLM, D_LLM);
        rope_kernel<<<MROWS, 256>>>(q, k);
        attn_scores<<<dim3(SEQ/64, SEQ/64, NB*NH), 256>>>(q, k, att);
        softmax_kernel<<<NB*NH*SEQ, 256>>>(att);
        attn_av<<<dim3(HD/64, SEQ/64, NB*NH), 256>>>(att, v, o);
        gemm_tf32<2><<<dim3(D_LLM/128, MROWS/128), 256, GEMM_SMEM>>>(o, wo, h, nullptr, h, MROWS, D_LLM, D_LLM);

        rmsnorm_kernel<<<MROWS, 256>>>(h, l2, x);
        gemm_tf32<0><<<dim3(D_FF/128, MROWS/128), 256, GEMM_SMEM>>>(x, wg, gate, nullptr, nullptr, MROWS, D_FF, D_LLM);
        gemm_tf32<0><<<dim3(D_FF/128, MROWS/128), 256, GEMM_SMEM>>>(x, wu, up,   nullptr, nullptr, MROWS, D_FF, D_LLM);
        silu_mul<<<(MROWS*(size_t)D_FF)/256, 256>>>(gate, up);
        gemm_tf32<2><<<dim3(D_LLM/128, MROWS/128), 256, GEMM_SMEM>>>(gate, wd, h, nullptr, h, MROWS, D_LLM, D_FF);
    }

    rmsnorm_kernel<<<MROWS, 256>>>(h, fnw, x);
    pool_kernel<<<dim3(D_LLM/256, NB), 256>>>(x, pool);
    head1_kernel<<<dim3(768/256, NB), 256>>>(pool, o1W, o1b, y1);
    head2_kernel<<<NB, 256>>>(y1, o2W, o2b, out);
}

// round 4
// speedup vs baseline: 1.8926x; 1.1365x over previous
#include <cuda_runtime.h>
#include <mma.h>
#include <math.h>
#include <stdint.h>

using namespace nvcuda;

// ---------------- problem constants ----------------
#define D_LLM 4096
#define D_FF  11008
#define NB    8
#define SEQ   256
#define SP    128
#define NH    32
#define HD    128
#define MROWS (NB*SEQ)          // 2048
#define MTV   (NB*128)          // 1024 text+vision rows
#define EPSR  1e-5f

// ---------------- scratch (device globals; no allocation) ----------------
__device__ float g_h   [MROWS*D_LLM];
__device__ float g_x   [MROWS*D_LLM];
__device__ float g_q   [MROWS*D_LLM];
__device__ float g_k   [MROWS*D_LLM];
__device__ float g_v   [MROWS*D_LLM];
__device__ float g_o   [MROWS*D_LLM];
__device__ float g_att [NB*NH*SEQ*SEQ];
__device__ float g_gate[MROWS*D_FF];
__device__ float g_up  [MROWS*D_FF];
__device__ float g_tv  [MTV*768];
__device__ float g_pool[NB*D_LLM];
__device__ float g_y1  [NB*768];

// ---------------- cp.async helpers ----------------
__device__ __forceinline__ void cp_async16(void* smem_dst, const void* gmem_src){
    uint32_t s = (uint32_t)__cvta_generic_to_shared(smem_dst);
    asm volatile("cp.async.cg.shared.global [%0], [%1], 16;\n" :: "r"(s), "l"(gmem_src));
}
__device__ __forceinline__ void cp_commit(){
    asm volatile("cp.async.commit_group;\n" ::: "memory");
}
template<int N>
__device__ __forceinline__ void cp_wait(){
    asm volatile("cp.async.wait_group %0;\n" :: "n"(N) : "memory");
}

// ---------------- block reductions ----------------
__device__ __forceinline__ float blockReduceSum(float v){
    __shared__ float sh[33];
    int lane = threadIdx.x & 31, w = threadIdx.x >> 5;
    #pragma unroll
    for (int o=16;o>0;o>>=1) v += __shfl_down_sync(0xffffffffu, v, o);
    if (lane==0) sh[w]=v;
    __syncthreads();
    if (threadIdx.x==0){
        float s = 0.f;
        int nw = (blockDim.x+31)>>5;
        for (int i=0;i<nw;i++) s += sh[i];
        sh[32]=s;
    }
    __syncthreads();
    float r = sh[32];
    __syncthreads();
    return r;
}

__device__ __forceinline__ float blockReduceMax(float v){
    __shared__ float sh[33];
    int lane = threadIdx.x & 31, w = threadIdx.x >> 5;
    #pragma unroll
    for (int o=16;o>0;o>>=1) v = fmaxf(v, __shfl_down_sync(0xffffffffu, v, o));
    if (lane==0) sh[w]=v;
    __syncthreads();
    if (threadIdx.x==0){
        float s = -3.0e38f;
        int nw = (blockDim.x+31)>>5;
        for (int i=0;i<nw;i++) s = fmaxf(s, sh[i]);
        sh[32]=s;
    }
    __syncthreads();
    float r = sh[32];
    __syncthreads();
    return r;
}

// ---------------- TF32 WMMA GEMM, 3-stage cp.async pipeline, 2 CTAs/SM ----------------
//   C[M,N] = A[M,K] @ B[K,N]
// EPI: 0 = plain store
//      1 = +bias[n], output rows remapped  out_row = blockIdx.y*256 + 128 + (m % 128)
//      2 = += resid (residual add)
// Requires: M%128==0, N%128==0, K%32==0, K/32 >= 3.
#define GEMM_STAGES 3
#define GEMM_AE (128*36)
#define GEMM_BE (32*132)
#define GEMM_SMEM (GEMM_STAGES*(GEMM_AE+GEMM_BE)*4)

template<int EPI>
__global__ void __launch_bounds__(256, 2)
gemm_tf32(const float* __restrict__ A, const float* __restrict__ B,
          float* __restrict__ C, const float* __restrict__ bias,
          const float* __restrict__ resid, int M, int N, int K)
{
    extern __shared__ float sm[];
    float* As = sm;                          // [ST][128][36]
    float* Bs = sm + GEMM_STAGES*GEMM_AE;    // [ST][32][132]

    const int tid = threadIdx.x;
    const int wid = tid >> 5;
    const int wm  = wid >> 2;       // 0..1   (64 rows each)
    const int wn  = wid & 3;        // 0..3   (32 cols each)
    const int m0  = blockIdx.y * 128;
    const int n0  = blockIdx.x * 128;
    const int KT  = K >> 5;         // chunks of 32

    wmma::fragment<wmma::accumulator,16,16,8,float> acc[4][2];
    #pragma unroll
    for (int i=0;i<4;i++)
        #pragma unroll
        for (int j=0;j<2;j++) wmma::fill_fragment(acc[i][j], 0.0f);

    // per-thread load coords (8 x 16B per chunk)
    auto load_chunk = [&](int st, int kt){
        const int k0 = kt << 5;
        float* Ad = As + st*GEMM_AE;
        float* Bd = Bs + st*GEMM_BE;
        #pragma unroll
        for (int it=0; it<4; it++){
            int qi = tid + it*256;
            int r  = qi >> 3, c = (qi & 7) << 2;          // A: 128 rows x 8 chunks
            cp_async16(Ad + r*36 + c, A + (size_t)(m0+r)*K + k0 + c);
            int rb = qi >> 5, cb = (qi & 31) << 2;        // B: 32 rows x 32 chunks
            cp_async16(Bd + rb*132 + cb, B + (size_t)(k0+rb)*N + n0 + cb);
        }
    };

    auto compute = [&](int st){
        float* Ab = As + st*GEMM_AE;
        float* Bb = Bs + st*GEMM_BE;
        #pragma unroll
        for (int ks=0; ks<32; ks+=8){
            wmma::fragment<wmma::matrix_b,16,16,8,wmma::precision::tf32,wmma::row_major> bf[2];
            #pragma unroll
            for (int j=0;j<2;j++){
                wmma::load_matrix_sync(bf[j], Bb + ks*132 + wn*32 + j*16, 132);
                #pragma unroll
                for (int t=0;t<bf[j].num_elements;t++) bf[j].x[t] = wmma::__float_to_tf32(bf[j].x[t]);
            }
            #pragma unroll
            for (int i=0;i<4;i++){
                wmma::fragment<wmma::matrix_a,16,16,8,wmma::precision::tf32,wmma::row_major> af;
                wmma::load_matrix_sync(af, Ab + (wm*64+i*16)*36 + ks, 36);
                #pragma unroll
                for (int t=0;t<af.num_elements;t++) af.x[t] = wmma::__float_to_tf32(af.x[t]);
                #pragma unroll
                for (int j=0;j<2;j++)
                    wmma::mma_sync(acc[i][j], af, bf[j], acc[i][j]);
            }
        }
    };

    // prologue: pre-issue STAGES-1 = 2 chunks
    #pragma unroll
    for (int s=0; s<GEMM_STAGES-1; s++){
        load_chunk(s, s);
        cp_commit();
    }

    int st = 0;
    for (int kt=0; kt<KT; kt++){
        cp_wait<GEMM_STAGES-2>();
        __syncthreads();           // single barrier: data ready AND stage (kt-1) free for reuse
        compute(st);
        int nc = kt + GEMM_STAGES - 1;
        if (nc < KT){
            int nst = st + (GEMM_STAGES-1); if (nst >= GEMM_STAGES) nst -= GEMM_STAGES;
            load_chunk(nst, nc);
        }
        cp_commit();
        st = (st+1 == GEMM_STAGES) ? 0 : st+1;
    }
    cp_wait<0>();
    __syncthreads();

    const int om0 = (EPI==1) ? (blockIdx.y*256 + 128) : m0;

    if (EPI==1){
        // broadcast bias into a 16x132 smem tile and add via accumulator frags
        float* bs = sm;
        for (int c=tid; c<128; c+=256){
            float bv = bias[n0+c];
            #pragma unroll
            for (int r=0;r<16;r++) bs[r*132+c]=bv;
        }
        __syncthreads();
        #pragma unroll
        for (int j=0;j<2;j++){
            wmma::fragment<wmma::accumulator,16,16,8,float> bfr;
            wmma::load_matrix_sync(bfr, bs + wn*32 + j*16, 132, wmma::mem_row_major);
            #pragma unroll
            for (int i=0;i<4;i++)
                #pragma unroll
                for (int t=0;t<8;t++) acc[i][j].x[t]+=bfr.x[t];
        }
    }

    #pragma unroll
    for (int i=0;i<4;i++)
        #pragma unroll
        for (int j=0;j<2;j++){
            size_t coff = (size_t)(om0 + wm*64 + i*16)*N + n0 + wn*32 + j*16;
            if (EPI==2){
                wmma::fragment<wmma::accumulator,16,16,8,float> rf;
                wmma::load_matrix_sync(rf, resid + coff, N, wmma::mem_row_major);
                #pragma unroll
                for (int t=0;t<8;t++) acc[i][j].x[t]+=rf.x[t];
            }
            wmma::store_matrix_sync(C + coff, acc[i][j], N, wmma::mem_row_major);
        }
}

// ---------------- embedding assembly ----------------
__global__ void gather_embed(const int* __restrict__ ids, const float* __restrict__ table,
                             float* __restrict__ h)
{
    int b = blockIdx.x >> 7, s = blockIdx.x & 127;
    int id = ids[b*SP + s];
    const float4* src = (const float4*)(table + (size_t)id*D_LLM);
    float4* dst = (float4*)(h + (size_t)(b*SEQ + s)*D_LLM);
    #pragma unroll
    for (int it=0; it<4; it++) dst[threadIdx.x + it*256] = src[threadIdx.x + it*256];
}

__global__ void stage_tv(const float* __restrict__ text, const float* __restrict__ vision,
                         float* __restrict__ tv)
{
    int b = blockIdx.x >> 7, r = blockIdx.x & 127;
    const float* src = (r < 64) ? (text + (size_t)(b*64 + r)*768)
                                : (vision + (size_t)(b*64 + (r-64))*768);
    float* dst = tv + (size_t)blockIdx.x*768;
    #pragma unroll
    for (int it=0; it<3; it++) dst[threadIdx.x + it*256] = src[threadIdx.x + it*256];
}

// ---------------- rmsnorm ----------------
__global__ void rmsnorm_kernel(const float* __restrict__ in, const float* __restrict__ w,
                               float* __restrict__ out)
{
    int row = blockIdx.x;
    const float* p = in + (size_t)row*D_LLM;
    float ss = 0.f;
    for (int d=threadIdx.x; d<D_LLM; d+=256){ float vv = p[d]; ss += vv*vv; }
    float tot = blockReduceSum(ss);
    float r = rsqrtf(tot*(1.0f/D_LLM) + EPSR);
    float* q = out + (size_t)row*D_LLM;
    for (int d=threadIdx.x; d<D_LLM; d+=256) q[d] = p[d]*r*w[d];
}

// ---------------- rope (in-place, q & k) ----------------
__global__ void rope_kernel(float* __restrict__ q, float* __restrict__ k)
{
    int m = blockIdx.x;
    int s = m & (SEQ-1);
    float* qr = q + (size_t)m*D_LLM;
    float* kr = k + (size_t)m*D_LLM;
    for (int p = threadIdx.x; p < NH*64; p += 256){
        int hh = p >> 6, i = p & 63;
        float invf = powf(10000.f, -(float)i * (1.f/64.f));
        float ang = (float)s * invf;
        float c, sn; sincosf(ang, &sn, &c);
        int b0 = hh*HD + i;
        float x1 = qr[b0], x2 = qr[b0+64];
        qr[b0]    = x1*c - x2*sn;
        qr[b0+64] = x2*c + x1*sn;
        x1 = kr[b0]; x2 = kr[b0+64];
        kr[b0]    = x1*c - x2*sn;
        kr[b0+64] = x2*c + x1*sn;
    }
}

// ---------------- attention: scores (Q K^T * scale), per (b,h), 64x64 tiles ----------------
__global__ void __launch_bounds__(256)
attn_scores(const float* __restrict__ Q, const float* __restrict__ K, float* __restrict__ att)
{
    int bh = blockIdx.z;
    int b = bh >> 5, h = bh & 31;
    int i0 = blockIdx.y*64, j0 = blockIdx.x*64;
    if (j0 > i0) return;                 // fully-masked tile: softmax never reads it

    __shared__ float Qs[64][33], Ks[64][33];
    int tid = threadIdx.x;
    int ty = tid >> 4, tx = tid & 15;
    float acc[4][4];
    #pragma unroll
    for (int r=0;r<4;r++)
        #pragma unroll
        for (int c=0;c<4;c++) acc[r][c]=0.f;

    const float* Qb = Q + (size_t)(b*SEQ + i0)*D_LLM + h*HD;
    const float* Kb = K + (size_t)(b*SEQ + j0)*D_LLM + h*HD;

    for (int d0=0; d0<HD; d0+=32){
        #pragma unroll
        for (int it=0; it<2; it++){
            int qi = tid + it*256;
            int r = qi >> 3, c = (qi & 7) << 2;
            float4 va = *(const float4*)(Qb + (size_t)r*D_LLM + d0 + c);
            Qs[r][c]=va.x; Qs[r][c+1]=va.y; Qs[r][c+2]=va.z; Qs[r][c+3]=va.w;
            float4 vb = *(const float4*)(Kb + (size_t)r*D_LLM + d0 + c);
            Ks[r][c]=vb.x; Ks[r][c+1]=vb.y; Ks[r][c+2]=vb.z; Ks[r][c+3]=vb.w;
        }
        __syncthreads();
        #pragma unroll
        for (int kk=0;kk<32;kk++){
            float a[4], bb[4];
            #pragma unroll
            for (int r=0;r<4;r++) a[r]=Qs[ty*4+r][kk];
            #pragma unroll
            for (int c=0;c<4;c++) bb[c]=Ks[tx*4+c][kk];
            #pragma unroll
            for (int r=0;r<4;r++)
                #pragma unroll
                for (int c=0;c<4;c++) acc[r][c] += a[r]*bb[c];
        }
        __syncthreads();
    }
    const float scale = 0.08838834764831845f;   // 1/sqrt(128)
    float* out = att + ((size_t)bh*SEQ + i0)*SEQ + j0;
    #pragma unroll
    for (int r=0;r<4;r++)
        #pragma unroll
        for (int c=0;c<4;c++)
            out[(size_t)(ty*4+r)*SEQ + tx*4+c] = acc[r][c]*scale;
}

// ---------------- softmax with causal mask (writes 0 for masked) ----------------
__global__ void softmax_kernel(float* __restrict__ att)
{
    int row = blockIdx.x;            // bh*256 + i
    int i = row & (SEQ-1);
    int j = threadIdx.x;
    float* p = att + (size_t)row*SEQ;
    float v = (j <= i) ? p[j] : -3.0e38f;
    float mx = blockReduceMax(v);
    float e = (j <= i) ? __expf(v - mx) : 0.f;
    float s = blockReduceSum(e);
    p[j] = e / s;
}

// ---------------- attention: O = P V, per (b,h), 64(i) x 64(d) tiles ----------------
__global__ void __launch_bounds__(256)
attn_av(const float* __restrict__ att, const float* __restrict__ V, float* __restrict__ O)
{
    int bh = blockIdx.z;
    int b = bh >> 5, h = bh & 31;
    int i0 = blockIdx.y*64, d0 = blockIdx.x*64;

    __shared__ float Ps[64][33], Vs[32][65];
    int tid = threadIdx.x;
    int ty = tid >> 4, tx = tid & 15;
    float acc[4][4];
    #pragma unroll
    for (int r=0;r<4;r++)
        #pragma unroll
        for (int c=0;c<4;c++) acc[r][c]=0.f;

    const float* Pb = att + ((size_t)bh*SEQ + i0)*SEQ;
    const float* Vb = V + (size_t)(b*SEQ)*D_LLM + h*HD + d0;

    int jend = i0 + 64;                 // rows beyond causal bound hold zeros anyway
    for (int j0=0; j0<jend; j0+=32){
        #pragma unroll
        for (int it=0; it<2; it++){
            int qi = tid + it*256;
            int r = qi >> 3, c = (qi & 7) << 2;           // P tile: 64x32
            float4 va = *(const float4*)(Pb + (size_t)r*SEQ + j0 + c);
            Ps[r][c]=va.x; Ps[r][c+1]=va.y; Ps[r][c+2]=va.z; Ps[r][c+3]=va.w;
            int rv = qi >> 4, cv = (qi & 15) << 2;        // V tile: 32x64
            float4 vb = *(const float4*)(Vb + (size_t)(j0+rv)*D_LLM + cv);
            Vs[rv][cv]=vb.x; Vs[rv][cv+1]=vb.y; Vs[rv][cv+2]=vb.z; Vs[rv][cv+3]=vb.w;
        }
        __syncthreads();
        #pragma unroll
        for (int kk=0;kk<32;kk++){
            float a[4], bb[4];
            #pragma unroll
            for (int r=0;r<4;r++) a[r]=Ps[ty*4+r][kk];
            #pragma unroll
            for (int c=0;c<4;c++) bb[c]=Vs[kk][tx*4+c];
            #pragma unroll
            for (int r=0;r<4;r++)
                #pragma unroll
                for (int c=0;c<4;c++) acc[r][c] += a[r]*bb[c];
        }
        __syncthreads();
    }
    float* out = O + (size_t)(b*SEQ + i0)*D_LLM + h*HD + d0;
    #pragma unroll
    for (int r=0;r<4;r++)
        #pragma unroll
        for (int c=0;c<4;c++)
            out[(size_t)(ty*4+r)*D_LLM + tx*4+c] = acc[r][c];
}

// ---------------- silu(gate) * up, in place into gate ----------------
__global__ void silu_mul(float* __restrict__ g, const float* __restrict__ u)
{
    size_t idx = (size_t)blockIdx.x*256 + threadIdx.x;
    float gv = g[idx];
    g[idx] = gv / (1.f + __expf(-gv)) * u[idx];
}

// ---------------- mean pool over sequence ----------------
__global__ void pool_kernel(const float* __restrict__ x, float* __restrict__ pool)
{
    int b = blockIdx.y;
    int d = blockIdx.x*256 + threadIdx.x;
    float acc = 0.f;
    const float* p = x + (size_t)(b*SEQ)*D_LLM + d;
    for (int s=0; s<SEQ; s++) acc += p[(size_t)s*D_LLM];
    pool[b*D_LLM + d] = acc * (1.f/SEQ);
}

// ---------------- head ----------------
__global__ void head1_kernel(const float* __restrict__ pool, const float* __restrict__ W1,
                             const float* __restrict__ b1, float* __restrict__ y1)
{
    __shared__ float sp[D_LLM];
    int b = blockIdx.y;
    for (int kk=threadIdx.x; kk<D_LLM; kk+=256) sp[kk]=pool[b*D_LLM+kk];
    __syncthreads();
    int n = blockIdx.x*256 + threadIdx.x;
    float acc = b1[n];
    for (int kk=0; kk<D_LLM; kk++) acc += sp[kk]*W1[(size_t)kk*768 + n];
    y1[b*768 + n] = acc;
}

__global__ void head2_kernel(const float* __restrict__ y1, const float* __restrict__ W2,
                             const float* __restrict__ b2, float* __restrict__ out)
{
    int b = blockIdx.x;
    float acc = 0.f;
    for (int kk=threadIdx.x; kk<768; kk+=256) acc += y1[b*768+kk]*W2[kk];
    float tot = blockReduceSum(acc);
    if (threadIdx.x==0) out[b] = tot + b2[0];
}

// ---------------- host orchestration ----------------
extern "C" void kernel_launch(void* const* d_in, const int* in_sizes, int n_in,
                              void* d_out, int out_size)
{
    const float* text   = (const float*)d_in[0];
    const float* vision = (const float*)d_in[1];
    const int*   ids    = (const int*)  d_in[2];
    const float* in_W   = (const float*)d_in[3];
    const float* in_b   = (const float*)d_in[4];
    const float* table  = (const float*)d_in[5];
    const float* Wq     = (const float*)d_in[6];
    const float* Wk     = (const float*)d_in[7];
    const float* Wv     = (const float*)d_in[8];
    const float* Wo     = (const float*)d_in[9];
    const float* ln1    = (const float*)d_in[10];
    const float* ln2    = (const float*)d_in[11];
    const float* Wg     = (const float*)d_in[12];
    const float* Wu     = (const float*)d_in[13];
    const float* Wd     = (const float*)d_in[14];
    const float* fnw    = (const float*)d_in[15];
    const float* o1W    = (const float*)d_in[16];
    const float* o1b    = (const float*)d_in[17];
    const float* o2W    = (const float*)d_in[18];
    const float* o2b    = (const float*)d_in[19];
    float* out = (float*)d_out;

    float *h,*x,*q,*k,*v,*o,*att,*gate,*up,*tv,*pool,*y1;
    cudaGetSymbolAddress((void**)&h,    g_h);
    cudaGetSymbolAddress((void**)&x,    g_x);
    cudaGetSymbolAddress((void**)&q,    g_q);
    cudaGetSymbolAddress((void**)&k,    g_k);
    cudaGetSymbolAddress((void**)&v,    g_v);
    cudaGetSymbolAddress((void**)&o,    g_o);
    cudaGetSymbolAddress((void**)&att,  g_att);
    cudaGetSymbolAddress((void**)&gate, g_gate);
    cudaGetSymbolAddress((void**)&up,   g_up);
    cudaGetSymbolAddress((void**)&tv,   g_tv);
    cudaGetSymbolAddress((void**)&pool, g_pool);
    cudaGetSymbolAddress((void**)&y1,   g_y1);

    // dynamic smem opt-in for the 3-stage GEMM (106 KB; 2 CTAs/SM)
    cudaFuncSetAttribute(gemm_tf32<0>, cudaFuncAttributeMaxDynamicSharedMemorySize, GEMM_SMEM);
    cudaFuncSetAttribute(gemm_tf32<1>, cudaFuncAttributeMaxDynamicSharedMemorySize, GEMM_SMEM);
    cudaFuncSetAttribute(gemm_tf32<2>, cudaFuncAttributeMaxDynamicSharedMemorySize, GEMM_SMEM);

    // --- embedding assembly: h[b, 0:128] = table[ids], h[b,128:256] = [text;vision] @ in_W + in_b
    gather_embed<<<NB*SP, 256>>>(ids, table, h);
    stage_tv<<<MTV, 256>>>(text, vision, tv);
    gemm_tf32<1><<<dim3(D_LLM/128, MTV/128), 256, GEMM_SMEM>>>(tv, in_W, h, in_b, nullptr, MTV, D_LLM, 768);

    for (int l=0; l<2; l++){
        const float* wq = Wq + (size_t)l*D_LLM*D_LLM;
        const float* wk = Wk + (size_t)l*D_LLM*D_LLM;
        const float* wv = Wv + (size_t)l*D_LLM*D_LLM;
        const float* wo = Wo + (size_t)l*D_LLM*D_LLM;
        const float* wg = Wg + (size_t)l*D_LLM*D_FF;
        const float* wu = Wu + (size_t)l*D_LLM*D_FF;
        const float* wd = Wd + (size_t)l*D_FF*D_LLM;
        const float* l1 = ln1 + (size_t)l*D_LLM;
        const float* l2 = ln2 + (size_t)l*D_LLM;

        rmsnorm_kernel<<<MROWS, 256>>>(h, l1, x);
        gemm_tf32<0><<<dim3(D_LLM/128, MROWS/128), 256, GEMM_SMEM>>>(x, wq, q, nullptr, nullptr, MROWS, D_LLM, D_LLM);
        gemm_tf32<0><<<dim3(D_LLM/128, MROWS/128), 256, GEMM_SMEM>>>(x, wk, k, nullptr, nullptr, MROWS, D_LLM, D_LLM);
        gemm_tf32<0><<<dim3(D_LLM/128, MROWS/128), 256, GEMM_SMEM>>>(x, wv, v, nullptr, nullptr, MROWS, D_LLM, D_LLM);
        rope_kernel<<<MROWS, 256>>>(q, k);
        attn_scores<<<dim3(SEQ/64, SEQ/64, NB*NH), 256>>>(q, k, att);
        softmax_kernel<<<NB*NH*SEQ, 256>>>(att);
        attn_av<<<dim3(HD/64, SEQ/64, NB*NH), 256>>>(att, v, o);
        gemm_tf32<2><<<dim3(D_LLM/128, MROWS/128), 256, GEMM_SMEM>>>(o, wo, h, nullptr, h, MROWS, D_LLM, D_LLM);

        rmsnorm_kernel<<<MROWS, 256>>>(h, l2, x);
        gemm_tf32<0><<<dim3(D_FF/128, MROWS/128), 256, GEMM_SMEM>>>(x, wg, gate, nullptr, nullptr, MROWS, D_FF, D_LLM);
        gemm_tf32<0><<<dim3(D_FF/128, MROWS/128), 256, GEMM_SMEM>>>(x, wu, up,   nullptr, nullptr, MROWS, D_FF, D_LLM);
        silu_mul<<<(MROWS*(size_t)D_FF)/256, 256>>>(gate, up);
        gemm_tf32<2><<<dim3(D_LLM/128, MROWS/128), 256, GEMM_SMEM>>>(gate, wd, h, nullptr, h, MROWS, D_LLM, D_FF);
    }

    rmsnorm_kernel<<<MROWS, 256>>>(h, fnw, x);
    pool_kernel<<<dim3(D_LLM/256, NB), 256>>>(x, pool);
    head1_kernel<<<dim3(768/256, NB), 256>>>(pool, o1W, o1b, y1);
    head2_kernel<<<NB, 256>>>(y1, o2W, o2b, out);
}

// round 7
// speedup vs baseline: 4.2879x; 2.2656x over previous
#include <cuda_runtime.h>
#include <mma.h>
#include <math.h>
#include <stdint.h>

// ---------------- problem constants ----------------
#define D_LLM 4096
#define D_FF  11008
#define NB    8
#define SEQ   256
#define SP    128
#define NH    32
#define HD    128
#define MROWS (NB*SEQ)          // 2048
#define MTV   (NB*128)          // 1024 text+vision rows
#define EPSR  1e-5f

// rounded-weight scratch layout (floats), same [K,N] shape as source (no transpose)
#define WSZ_ATT  (D_LLM*D_LLM)
#define WSZ_FF   (D_LLM*D_FF)
#define L_WQ   0
#define L_WK   (1*WSZ_ATT)
#define L_WV   (2*WSZ_ATT)
#define L_WO   (3*WSZ_ATT)
#define L_WG   (4*WSZ_ATT)
#define L_WU   (4*WSZ_ATT + WSZ_FF)
#define L_WD   (4*WSZ_ATT + 2*WSZ_FF)
#define LAYER_STRIDE (4*WSZ_ATT + 3*WSZ_FF)

// ---------------- scratch (device globals; no allocation) ----------------
__device__ float g_h   [MROWS*D_LLM];
__device__ float g_x   [MROWS*D_LLM];
__device__ float g_q   [MROWS*D_LLM];
__device__ float g_k   [MROWS*D_LLM];
__device__ float g_v   [MROWS*D_LLM];
__device__ float g_o   [MROWS*D_LLM];
__device__ float g_att [NB*NH*SEQ*SEQ];
__device__ float g_gate[MROWS*D_FF];
__device__ float g_up  [MROWS*D_FF];
__device__ float g_tv  [MTV*768];
__device__ float g_pool[NB*D_LLM];
__device__ float g_y1  [NB*768];
__device__ float g_wR  [2*LAYER_STRIDE];      // tf32-rounded weights
__device__ float g_inWR[768*D_LLM];           // tf32-rounded in_W

// ---------------- helpers ----------------
__device__ __forceinline__ float rn_tf32(float v){
    float r;
    asm("cvt.rna.tf32.f32 %0, %1;" : "=f"(r) : "f"(v));
    return r;
}

__device__ __forceinline__ void cp_async16_s(uint32_t saddr, const void* gmem_src){
    asm volatile("cp.async.cg.shared.global [%0], [%1], 16;\n" :: "r"(saddr), "l"(gmem_src));
}
__device__ __forceinline__ void cp_commit(){
    asm volatile("cp.async.commit_group;\n" ::: "memory");
}
template<int N>
__device__ __forceinline__ void cp_wait(){
    asm volatile("cp.async.wait_group %0;\n" :: "n"(N) : "memory");
}

__device__ __forceinline__ void mma_tf32(float* d, uint32_t a0, uint32_t a1, uint32_t a2, uint32_t a3,
                                         uint32_t b0, uint32_t b1){
    asm volatile(
        "mma.sync.aligned.m16n8k8.row.col.f32.tf32.tf32.f32 "
        "{%0,%1,%2,%3}, {%4,%5,%6,%7}, {%8,%9}, {%0,%1,%2,%3};"
        : "+f"(d[0]), "+f"(d[1]), "+f"(d[2]), "+f"(d[3])
        : "r"(a0), "r"(a1), "r"(a2), "r"(a3), "r"(b0), "r"(b1));
}

// ---------------- block reductions ----------------
__device__ __forceinline__ float blockReduceSum(float v){
    __shared__ float sh[33];
    int lane = threadIdx.x & 31, w = threadIdx.x >> 5;
    #pragma unroll
    for (int o=16;o>0;o>>=1) v += __shfl_down_sync(0xffffffffu, v, o);
    if (lane==0) sh[w]=v;
    __syncthreads();
    if (threadIdx.x==0){
        float s = 0.f;
        int nw = (blockDim.x+31)>>5;
        for (int i=0;i<nw;i++) s += sh[i];
        sh[32]=s;
    }
    __syncthreads();
    float r = sh[32];
    __syncthreads();
    return r;
}
__device__ __forceinline__ float blockReduceMax(float v){
    __shared__ float sh[33];
    int lane = threadIdx.x & 31, w = threadIdx.x >> 5;
    #pragma unroll
    for (int o=16;o>0;o>>=1) v = fmaxf(v, __shfl_down_sync(0xffffffffu, v, o));
    if (lane==0) sh[w]=v;
    __syncthreads();
    if (threadIdx.x==0){
        float s = -3.0e38f;
        int nw = (blockDim.x+31)>>5;
        for (int i=0;i<nw;i++) s = fmaxf(s, sh[i]);
        sh[32]=s;
    }
    __syncthreads();
    float r = sh[32];
    __syncthreads();
    return r;
}

// ---------------- tf32 rounding pass (weights) ----------------
__global__ void round_rn(const float* __restrict__ in, float* __restrict__ out, size_t n4)
{
    size_t i = (size_t)blockIdx.x*blockDim.x + threadIdx.x;
    if (i >= n4) return;
    float4 v = ((const float4*)in)[i];
    v.x = rn_tf32(v.x); v.y = rn_tf32(v.y); v.z = rn_tf32(v.z); v.w = rn_tf32(v.w);
    ((float4*)out)[i] = v;
}

// ---------------- TF32 mma.sync GEMM, 3-stage cp.async, 2 CTAs/SM ----------------
//   C[M,N] = A[M,K] @ B[K,N]   (A rows tf32-rounded by producers, B pre-rounded)
// EPI: 0 plain, 1 +bias & row-remap (in_proj), 2 += resid
// Requires: M%128==0, N%128==0, K%32==0, K/32 >= 3.
#define TCS 3
#define A_STG 4608              // 128*36 floats
#define B_STG 4352              // 32*136 floats
#define TC_SMEM ((TCS*(A_STG+B_STG))*4)

template<int EPI>
__global__ void __launch_bounds__(256, 2)
gemm_mma(const float* __restrict__ A, const float* __restrict__ B,
         float* __restrict__ C, const float* __restrict__ bias,
         const float* __restrict__ resid, int M, int N, int K)
{
    extern __shared__ float sm[];
    float* AsAll = sm;                       // [TCS][128][36]
    float* BsAll = sm + TCS*A_STG;           // [TCS][32][136]
    const uint32_t sb = (uint32_t)__cvta_generic_to_shared(sm);

    const int tid = threadIdx.x;
    const int wid = tid >> 5, lane = tid & 31;
    const int g   = lane >> 2, tig = lane & 3;
    const int wm  = wid >> 2;                // 0..1 (64 rows)
    const int wn  = wid & 3;                 // 0..3 (32 cols)
    const int m0  = blockIdx.x * 128;
    const int n0  = blockIdx.y * 128;
    const int KT  = K >> 5;

    float acc[4][4][4];                      // [mf][nf][reg]
    #pragma unroll
    for (int i=0;i<4;i++)
        #pragma unroll
        for (int j=0;j<4;j++)
            #pragma unroll
            for (int t=0;t<4;t++) acc[i][j][t]=0.f;

    auto load_chunk = [&](int st, int kc){
        const int k0 = kc << 5;
        const uint32_t ab = sb + (uint32_t)(st*A_STG*4);
        const uint32_t bb = sb + (uint32_t)((TCS*A_STG + st*B_STG)*4);
        #pragma unroll
        for (int it=0; it<4; it++){
            int qi = tid + it*256;
            int r  = qi >> 3, c4 = qi & 7;             // A: 128 rows x 8 float4
            cp_async16_s(ab + (uint32_t)(r*144 + c4*16), A + (size_t)(m0+r)*K + k0 + c4*4);
            int rb = qi >> 5, cb = qi & 31;            // B: 32 rows x 32 float4
            cp_async16_s(bb + (uint32_t)(rb*544 + cb*16), B + (size_t)(k0+rb)*N + n0 + cb*4);
        }
    };

    auto compute = [&](int st){
        const float* As = AsAll + st*A_STG;
        const float* Bs = BsAll + st*B_STG;
        #pragma unroll
        for (int ks=0; ks<32; ks+=8){
            uint32_t bfr[4][2];
            #pragma unroll
            for (int nf=0; nf<4; nf++){
                int col = wn*32 + nf*8 + g;
                bfr[nf][0] = __float_as_uint(Bs[(ks+tig  )*136 + col]);
                bfr[nf][1] = __float_as_uint(Bs[(ks+tig+4)*136 + col]);
            }
            #pragma unroll
            for (int mf=0; mf<4; mf++){
                int row = wm*64 + mf*16;
                uint32_t a0 = __float_as_uint(As[(row+g  )*36 + ks + tig  ]);
                uint32_t a1 = __float_as_uint(As[(row+g+8)*36 + ks + tig  ]);
                uint32_t a2 = __float_as_uint(As[(row+g  )*36 + ks + tig+4]);
                uint32_t a3 = __float_as_uint(As[(row+g+8)*36 + ks + tig+4]);
                #pragma unroll
                for (int nf=0; nf<4; nf++)
                    mma_tf32(acc[mf][nf], a0, a1, a2, a3, bfr[nf][0], bfr[nf][1]);
            }
        }
    };

    load_chunk(0, 0); cp_commit();
    load_chunk(1, 1); cp_commit();

    int st = 0;
    for (int kt=0; kt<KT; kt++){
        cp_wait<1>();
        __syncthreads();
        compute(st);
        int nc = kt + 2;
        if (nc < KT){
            int ns = st + 2; if (ns >= TCS) ns -= TCS;
            load_chunk(ns, nc);
        }
        cp_commit();
        st = (st+1 == TCS) ? 0 : st+1;
    }

    // epilogue
    const int om0 = (EPI==1) ? (blockIdx.x*256 + 128) : m0;
    #pragma unroll
    for (int mf=0; mf<4; mf++){
        int r0 = om0 + wm*64 + mf*16 + g;
        #pragma unroll
        for (int nf=0; nf<4; nf++){
            int c0 = n0 + wn*32 + nf*8 + 2*tig;
            float* p0 = C + (size_t)r0*N + c0;
            float* p1 = C + (size_t)(r0+8)*N + c0;
            float2 v0 = make_float2(acc[mf][nf][0], acc[mf][nf][1]);
            float2 v1 = make_float2(acc[mf][nf][2], acc[mf][nf][3]);
            if (EPI==2){
                const float2 r0v = *(const float2*)(resid + (size_t)r0*N + c0);
                const float2 r1v = *(const float2*)(resid + (size_t)(r0+8)*N + c0);
                v0.x += r0v.x; v0.y += r0v.y; v1.x += r1v.x; v1.y += r1v.y;
            } else if (EPI==1){
                float b0 = bias[c0], b1 = bias[c0+1];
                v0.x += b0; v0.y += b1; v1.x += b0; v1.y += b1;
            }
            *(float2*)p0 = v0;
            *(float2*)p1 = v1;
        }
    }
}

// ---------------- embedding assembly ----------------
__global__ void gather_embed(const int* __restrict__ ids, const float* __restrict__ table,
                             float* __restrict__ h)
{
    int b = blockIdx.x >> 7, s = blockIdx.x & 127;
    int id = ids[b*SP + s];
    const float4* src = (const float4*)(table + (size_t)id*D_LLM);
    float4* dst = (float4*)(h + (size_t)(b*SEQ + s)*D_LLM);
    #pragma unroll
    for (int it=0; it<4; it++) dst[threadIdx.x + it*256] = src[threadIdx.x + it*256];
}

__global__ void stage_tv(const float* __restrict__ text, const float* __restrict__ vision,
                         float* __restrict__ tv)
{
    int b = blockIdx.x >> 7, r = blockIdx.x & 127;
    const float* src = (r < 64) ? (text + (size_t)(b*64 + r)*768)
                                : (vision + (size_t)(b*64 + (r-64))*768);
    float* dst = tv + (size_t)blockIdx.x*768;
    #pragma unroll
    for (int it=0; it<3; it++) dst[threadIdx.x + it*256] = rn_tf32(src[threadIdx.x + it*256]);
}

// ---------------- rmsnorm (RND: round output to tf32 for GEMM-A use) ----------------
template<bool RND>
__global__ void rmsnorm_kernel(const float* __restrict__ in, const float* __restrict__ w,
                               float* __restrict__ out)
{
    int row = blockIdx.x;
    const float* p = in + (size_t)row*D_LLM;
    float ss = 0.f;
    for (int d=threadIdx.x; d<D_LLM; d+=256){ float vv = p[d]; ss += vv*vv; }
    float tot = blockReduceSum(ss);
    float r = rsqrtf(tot*(1.0f/D_LLM) + EPSR);
    float* q = out + (size_t)row*D_LLM;
    for (int d=threadIdx.x; d<D_LLM; d+=256){
        float v = p[d]*r*w[d];
        q[d] = RND ? rn_tf32(v) : v;
    }
}

// ---------------- rope (in-place, q & k) ----------------
__global__ void rope_kernel(float* __restrict__ q, float* __restrict__ k)
{
    int m = blockIdx.x;
    int s = m & (SEQ-1);
    float* qr = q + (size_t)m*D_LLM;
    float* kr = k + (size_t)m*D_LLM;
    for (int p = threadIdx.x; p < NH*64; p += 256){
        int hh = p >> 6, i = p & 63;
        float invf = powf(10000.f, -(float)i * (1.f/64.f));
        float ang = (float)s * invf;
        float c, sn; sincosf(ang, &sn, &c);
        int b0 = hh*HD + i;
        float x1 = qr[b0], x2 = qr[b0+64];
        qr[b0]    = x1*c - x2*sn;
        qr[b0+64] = x2*c + x1*sn;
        x1 = kr[b0]; x2 = kr[b0+64];
        kr[b0]    = x1*c - x2*sn;
        kr[b0+64] = x2*c + x1*sn;
    }
}

// ---------------- attention: scores (Q K^T * scale), per (b,h), 64x64 tiles ----------------
__global__ void __launch_bounds__(256)
attn_scores(const float* __restrict__ Q, const float* __restrict__ K, float* __restrict__ att)
{
    int bh = blockIdx.z;
    int b = bh >> 5, h = bh & 31;
    int i0 = blockIdx.y*64, j0 = blockIdx.x*64;
    if (j0 > i0) return;

    __shared__ float Qs[64][33], Ks[64][33];
    int tid = threadIdx.x;
    int ty = tid >> 4, tx = tid & 15;
    float acc[4][4];
    #pragma unroll
    for (int r=0;r<4;r++)
        #pragma unroll
        for (int c=0;c<4;c++) acc[r][c]=0.f;

    const float* Qb = Q + (size_t)(b*SEQ + i0)*D_LLM + h*HD;
    const float* Kb = K + (size_t)(b*SEQ + j0)*D_LLM + h*HD;

    for (int d0=0; d0<HD; d0+=32){
        #pragma unroll
        for (int it=0; it<2; it++){
            int qi = tid + it*256;
            int r = qi >> 3, c = (qi & 7) << 2;
            float4 va = *(const float4*)(Qb + (size_t)r*D_LLM + d0 + c);
            Qs[r][c]=va.x; Qs[r][c+1]=va.y; Qs[r][c+2]=va.z; Qs[r][c+3]=va.w;
            float4 vb = *(const float4*)(Kb + (size_t)r*D_LLM + d0 + c);
            Ks[r][c]=vb.x; Ks[r][c+1]=vb.y; Ks[r][c+2]=vb.z; Ks[r][c+3]=vb.w;
        }
        __syncthreads();
        #pragma unroll
        for (int kk=0;kk<32;kk++){
            float a[4], bb[4];
            #pragma unroll
            for (int r=0;r<4;r++) a[r]=Qs[ty*4+r][kk];
            #pragma unroll
            for (int c=0;c<4;c++) bb[c]=Ks[tx*4+c][kk];
            #pragma unroll
            for (int r=0;r<4;r++)
                #pragma unroll
                for (int c=0;c<4;c++) acc[r][c] += a[r]*bb[c];
        }
        __syncthreads();
    }
    const float scale = 0.08838834764831845f;
    float* out = att + ((size_t)bh*SEQ + i0)*SEQ + j0;
    #pragma unroll
    for (int r=0;r<4;r++)
        #pragma unroll
        for (int c=0;c<4;c++)
            out[(size_t)(ty*4+r)*SEQ + tx*4+c] = acc[r][c]*scale;
}

// ---------------- softmax with causal mask ----------------
__global__ void softmax_kernel(float* __restrict__ att)
{
    int row = blockIdx.x;
    int i = row & (SEQ-1);
    int j = threadIdx.x;
    float* p = att + (size_t)row*SEQ;
    float v = (j <= i) ? p[j] : -3.0e38f;
    float mx = blockReduceMax(v);
    float e = (j <= i) ? __expf(v - mx) : 0.f;
    float s = blockReduceSum(e);
    p[j] = e / s;
}

// ---------------- attention: O = P V (rounded: A-input of Wo GEMM) ----------------
__global__ void __launch_bounds__(256)
attn_av(const float* __restrict__ att, const float* __restrict__ V, float* __restrict__ O)
{
    int bh = blockIdx.z;
    int b = bh >> 5, h = bh & 31;
    int i0 = blockIdx.y*64, d0 = blockIdx.x*64;

    __shared__ float Ps[64][33], Vs[32][65];
    int tid = threadIdx.x;
    int ty = tid >> 4, tx = tid & 15;
    float acc[4][4];
    #pragma unroll
    for (int r=0;r<4;r++)
        #pragma unroll
        for (int c=0;c<4;c++) acc[r][c]=0.f;

    const float* Pb = att + ((size_t)bh*SEQ + i0)*SEQ;
    const float* Vb = V + (size_t)(b*SEQ)*D_LLM + h*HD + d0;

    int jend = i0 + 64;
    for (int j0=0; j0<jend; j0+=32){
        #pragma unroll
        for (int it=0; it<2; it++){
            int qi = tid + it*256;
            int r = qi >> 3, c = (qi & 7) << 2;
            float4 va = *(const float4*)(Pb + (size_t)r*SEQ + j0 + c);
            Ps[r][c]=va.x; Ps[r][c+1]=va.y; Ps[r][c+2]=va.z; Ps[r][c+3]=va.w;
            int rv = qi >> 4, cv = (qi & 15) << 2;
            float4 vb = *(const float4*)(Vb + (size_t)(j0+rv)*D_LLM + cv);
            Vs[rv][cv]=vb.x; Vs[rv][cv+1]=vb.y; Vs[rv][cv+2]=vb.z; Vs[rv][cv+3]=vb.w;
        }
        __syncthreads();
        #pragma unroll
        for (int kk=0;kk<32;kk++){
            float a[4], bb[4];
            #pragma unroll
            for (int r=0;r<4;r++) a[r]=Ps[ty*4+r][kk];
            #pragma unroll
            for (int c=0;c<4;c++) bb[c]=Vs[kk][tx*4+c];
            #pragma unroll
            for (int r=0;r<4;r++)
                #pragma unroll
                for (int c=0;c<4;c++) acc[r][c] += a[r]*bb[c];
        }
        __syncthreads();
    }
    float* out = O + (size_t)(b*SEQ + i0)*D_LLM + h*HD + d0;
    #pragma unroll
    for (int r=0;r<4;r++)
        #pragma unroll
        for (int c=0;c<4;c++)
            out[(size_t)(ty*4+r)*D_LLM + tx*4+c] = rn_tf32(acc[r][c]);
}

// ---------------- silu(gate) * up -> gate (rounded: A-input of Wd GEMM) ----------------
__global__ void silu_mul(float* __restrict__ g, const float* __restrict__ u)
{
    size_t idx = (size_t)blockIdx.x*256 + threadIdx.x;
    float gv = g[idx];
    g[idx] = rn_tf32(gv / (1.f + __expf(-gv)) * u[idx]);
}

// ---------------- mean pool over sequence ----------------
__global__ void pool_kernel(const float* __restrict__ x, float* __restrict__ pool)
{
    int b = blockIdx.y;
    int d = blockIdx.x*256 + threadIdx.x;
    float acc = 0.f;
    const float* p = x + (size_t)(b*SEQ)*D_LLM + d;
    for (int s=0; s<SEQ; s++) acc += p[(size_t)s*D_LLM];
    pool[b*D_LLM + d] = acc * (1.f/SEQ);
}

// ---------------- head ----------------
__global__ void head1_kernel(const float* __restrict__ pool, const float* __restrict__ W1,
                             const float* __restrict__ b1, float* __restrict__ y1)
{
    __shared__ float sp[D_LLM];
    int b = blockIdx.y;
    for (int kk=threadIdx.x; kk<D_LLM; kk+=256) sp[kk]=pool[b*D_LLM+kk];
    __syncthreads();
    int n = blockIdx.x*256 + threadIdx.x;
    float acc = b1[n];
    for (int kk=0; kk<D_LLM; kk++) acc += sp[kk]*W1[(size_t)kk*768 + n];
    y1[b*768 + n] = acc;
}

__global__ void head2_kernel(const float* __restrict__ y1, const float* __restrict__ W2,
                             const float* __restrict__ b2, float* __restrict__ out)
{
    int b = blockIdx.x;
    float acc = 0.f;
    for (int kk=threadIdx.x; kk<768; kk+=256) acc += y1[b*768+kk]*W2[kk];
    float tot = blockReduceSum(acc);
    if (threadIdx.x==0) out[b] = tot + b2[0];
}

// ---------------- host orchestration ----------------
extern "C" void kernel_launch(void* const* d_in, const int* in_sizes, int n_in,
                              void* d_out, int out_size)
{
    const float* text   = (const float*)d_in[0];
    const float* vision = (const float*)d_in[1];
    const int*   ids    = (const int*)  d_in[2];
    const float* in_W   = (const float*)d_in[3];
    const float* in_b   = (const float*)d_in[4];
    const float* table  = (const float*)d_in[5];
    const float* Wq     = (const float*)d_in[6];
    const float* Wk     = (const float*)d_in[7];
    const float* Wv     = (const float*)d_in[8];
    const float* Wo     = (const float*)d_in[9];
    const float* ln1    = (const float*)d_in[10];
    const float* ln2    = (const float*)d_in[11];
    const float* Wg     = (const float*)d_in[12];
    const float* Wu     = (const float*)d_in[13];
    const float* Wd     = (const float*)d_in[14];
    const float* fnw    = (const float*)d_in[15];
    const float* o1W    = (const float*)d_in[16];
    const float* o1b    = (const float*)d_in[17];
    const float* o2W    = (const float*)d_in[18];
    const float* o2b    = (const float*)d_in[19];
    float* out = (float*)d_out;

    float *h,*x,*q,*k,*v,*o,*att,*gate,*up,*tv,*pool,*y1,*wR,*inWR;
    cudaGetSymbolAddress((void**)&h,    g_h);
    cudaGetSymbolAddress((void**)&x,    g_x);
    cudaGetSymbolAddress((void**)&q,    g_q);
    cudaGetSymbolAddress((void**)&k,    g_k);
    cudaGetSymbolAddress((void**)&v,    g_v);
    cudaGetSymbolAddress((void**)&o,    g_o);
    cudaGetSymbolAddress((void**)&att,  g_att);
    cudaGetSymbolAddress((void**)&gate, g_gate);
    cudaGetSymbolAddress((void**)&up,   g_up);
    cudaGetSymbolAddress((void**)&tv,   g_tv);
    cudaGetSymbolAddress((void**)&pool, g_pool);
    cudaGetSymbolAddress((void**)&y1,   g_y1);
    cudaGetSymbolAddress((void**)&wR,   g_wR);
    cudaGetSymbolAddress((void**)&inWR, g_inWR);

    cudaFuncSetAttribute(gemm_mma<0>, cudaFuncAttributeMaxDynamicSharedMemorySize, TC_SMEM);
    cudaFuncSetAttribute(gemm_mma<1>, cudaFuncAttributeMaxDynamicSharedMemorySize, TC_SMEM);
    cudaFuncSetAttribute(gemm_mma<2>, cudaFuncAttributeMaxDynamicSharedMemorySize, TC_SMEM);

    // one-time (per launch) tf32 rounding of all weights
    auto roundw = [&](const float* src, float* dst, size_t n){
        size_t n4 = n >> 2;
        round_rn<<<(unsigned)((n4 + 255)/256), 256>>>(src, dst, n4);
    };
    roundw(in_W, inWR, (size_t)768*D_LLM);
    for (int l=0; l<2; l++){
        float* wl = wR + (size_t)l*LAYER_STRIDE;
        roundw(Wq + (size_t)l*WSZ_ATT, wl + L_WQ, WSZ_ATT);
        roundw(Wk + (size_t)l*WSZ_ATT, wl + L_WK, WSZ_ATT);
        roundw(Wv + (size_t)l*WSZ_ATT, wl + L_WV, WSZ_ATT);
        roundw(Wo + (size_t)l*WSZ_ATT, wl + L_WO, WSZ_ATT);
        roundw(Wg + (size_t)l*WSZ_FF,  wl + L_WG, WSZ_FF);
        roundw(Wu + (size_t)l*WSZ_FF,  wl + L_WU, WSZ_FF);
        roundw(Wd + (size_t)l*WSZ_FF,  wl + L_WD, WSZ_FF);
    }

    // --- embedding assembly
    gather_embed<<<NB*SP, 256>>>(ids, table, h);
    stage_tv<<<MTV, 256>>>(text, vision, tv);
    gemm_mma<1><<<dim3(MTV/128, D_LLM/128), 256, TC_SMEM>>>(tv, inWR, h, in_b, nullptr, MTV, D_LLM, 768);

    for (int l=0; l<2; l++){
        const float* wq = wR + (size_t)l*LAYER_STRIDE + L_WQ;
        const float* wk = wR + (size_t)l*LAYER_STRIDE + L_WK;
        const float* wv = wR + (size_t)l*LAYER_STRIDE + L_WV;
        const float* wo = wR + (size_t)l*LAYER_STRIDE + L_WO;
        const float* wg = wR + (size_t)l*LAYER_STRIDE + L_WG;
        const float* wu = wR + (size_t)l*LAYER_STRIDE + L_WU;
        const float* wd = wR + (size_t)l*LAYER_STRIDE + L_WD;
        const float* l1 = ln1 + (size_t)l*D_LLM;
        const float* l2 = ln2 + (size_t)l*D_LLM;

        rmsnorm_kernel<true><<<MROWS, 256>>>(h, l1, x);
        gemm_mma<0><<<dim3(MROWS/128, D_LLM/128), 256, TC_SMEM>>>(x, wq, q, nullptr, nullptr, MROWS, D_LLM, D_LLM);
        gemm_mma<0><<<dim3(MROWS/128, D_LLM/128), 256, TC_SMEM>>>(x, wk, k, nullptr, nullptr, MROWS, D_LLM, D_LLM);
        gemm_mma<0><<<dim3(MROWS/128, D_LLM/128), 256, TC_SMEM>>>(x, wv, v, nullptr, nullptr, MROWS, D_LLM, D_LLM);
        rope_kernel<<<MROWS, 256>>>(q, k);
        attn_scores<<<dim3(SEQ/64, SEQ/64, NB*NH), 256>>>(q, k, att);
        softmax_kernel<<<NB*NH*SEQ, 256>>>(att);
        attn_av<<<dim3(HD/64, SEQ/64, NB*NH), 256>>>(att, v, o);
        gemm_mma<2><<<dim3(MROWS/128, D_LLM/128), 256, TC_SMEM>>>(o, wo, h, nullptr, h, MROWS, D_LLM, D_LLM);

        rmsnorm_kernel<true><<<MROWS, 256>>>(h, l2, x);
        gemm_mma<0><<<dim3(MROWS/128, D_FF/128), 256, TC_SMEM>>>(x, wg, gate, nullptr, nullptr, MROWS, D_FF, D_LLM);
        gemm_mma<0><<<dim3(MROWS/128, D_FF/128), 256, TC_SMEM>>>(x, wu, up,   nullptr, nullptr, MROWS, D_FF, D_LLM);
        silu_mul<<<(MROWS*(size_t)D_FF)/256, 256>>>(gate, up);
        gemm_mma<2><<<dim3(MROWS/128, D_LLM/128), 256, TC_SMEM>>>(gate, wd, h, nullptr, h, MROWS, D_LLM, D_FF);
    }

    rmsnorm_kernel<false><<<MROWS, 256>>>(h, fnw, x);
    pool_kernel<<<dim3(D_LLM/256, NB), 256>>>(x, pool);
    head1_kernel<<<dim3(768/256, NB), 256>>>(pool, o1W, o1b, y1);
    head2_kernel<<<NB, 256>>>(y1, o2W, o2b, out);
}

// round 8
// speedup vs baseline: 4.4266x; 1.0324x over previous
#include <cuda_runtime.h>
#include <mma.h>
#include <math.h>
#include <stdint.h>

// ---------------- problem constants ----------------
#define D_LLM 4096
#define D_FF  11008
#define NB    8
#define SEQ   256
#define SP    128
#define NH    32
#define HD    128
#define MROWS (NB*SEQ)          // 2048
#define MTV   (NB*128)          // 1024 text+vision rows
#define EPSR  1e-5f

// ---------------- scratch (device globals; no allocation) ----------------
__device__ float g_h   [MROWS*D_LLM];
__device__ float g_x   [MROWS*D_LLM];
__device__ float g_q   [MROWS*D_LLM];
__device__ float g_k   [MROWS*D_LLM];
__device__ float g_v   [MROWS*D_LLM];
__device__ float g_o   [MROWS*D_LLM];
__device__ float g_att [NB*NH*SEQ*SEQ];
__device__ float g_gate[MROWS*D_FF];
__device__ float g_up  [MROWS*D_FF];
__device__ float g_tv  [MTV*768];
__device__ float g_pool[NB*D_LLM];
__device__ float g_y1  [NB*768];

// ---------------- helpers ----------------
__device__ __forceinline__ float rn_tf32(float v){
    float r;
    asm("cvt.rna.tf32.f32 %0, %1;" : "=f"(r) : "f"(v));
    return r;
}
__device__ __forceinline__ uint32_t rn_tf32_bits(float v){
    float r;
    asm("cvt.rna.tf32.f32 %0, %1;" : "=f"(r) : "f"(v));
    return __float_as_uint(r);
}

__device__ __forceinline__ void cp_async16_s(uint32_t saddr, const void* gmem_src){
    asm volatile("cp.async.cg.shared.global [%0], [%1], 16;\n" :: "r"(saddr), "l"(gmem_src));
}
__device__ __forceinline__ void cp_commit(){
    asm volatile("cp.async.commit_group;\n" ::: "memory");
}
template<int N>
__device__ __forceinline__ void cp_wait(){
    asm volatile("cp.async.wait_group %0;\n" :: "n"(N) : "memory");
}

__device__ __forceinline__ void mma_tf32(float* d, uint32_t a0, uint32_t a1, uint32_t a2, uint32_t a3,
                                         uint32_t b0, uint32_t b1){
    asm volatile(
        "mma.sync.aligned.m16n8k8.row.col.f32.tf32.tf32.f32 "
        "{%0,%1,%2,%3}, {%4,%5,%6,%7}, {%8,%9}, {%0,%1,%2,%3};"
        : "+f"(d[0]), "+f"(d[1]), "+f"(d[2]), "+f"(d[3])
        : "r"(a0), "r"(a1), "r"(a2), "r"(a3), "r"(b0), "r"(b1));
}

// ---------------- block reductions ----------------
__device__ __forceinline__ float blockReduceSum(float v){
    __shared__ float sh[33];
    int lane = threadIdx.x & 31, w = threadIdx.x >> 5;
    #pragma unroll
    for (int o=16;o>0;o>>=1) v += __shfl_down_sync(0xffffffffu, v, o);
    if (lane==0) sh[w]=v;
    __syncthreads();
    if (threadIdx.x==0){
        float s = 0.f;
        int nw = (blockDim.x+31)>>5;
        for (int i=0;i<nw;i++) s += sh[i];
        sh[32]=s;
    }
    __syncthreads();
    float r = sh[32];
    __syncthreads();
    return r;
}
__device__ __forceinline__ float blockReduceMax(float v){
    __shared__ float sh[33];
    int lane = threadIdx.x & 31, w = threadIdx.x >> 5;
    #pragma unroll
    for (int o=16;o>0;o>>=1) v = fmaxf(v, __shfl_down_sync(0xffffffffu, v, o));
    if (lane==0) sh[w]=v;
    __syncthreads();
    if (threadIdx.x==0){
        float s = -3.0e38f;
        int nw = (blockDim.x+31)>>5;
        for (int i=0;i<nw;i++) s = fmaxf(s, sh[i]);
        sh[32]=s;
    }
    __syncthreads();
    float r = sh[32];
    __syncthreads();
    return r;
}

// ---------------- TF32 mma.sync GEMM, 256x128 tile, 3-stage cp.async ----------------
//   C[M,N] = A[M,K] @ B[K,N]
//   A rows pre-rounded to tf32 by producers; B rounded in-register (cvt.rna) before mma.
// EPI: 0 plain, 1 +bias & row-remap (in_proj), 2 += resid
// Requires: M%256==0, N%128==0, K%32==0, K/32 >= 3.
#define TCS 3
#define BM 256
#define BN 128
#define A_STG (BM*36)            // 9216 floats
#define B_STG (32*136)           // 4352 floats
#define TC_SMEM ((TCS*(A_STG+B_STG))*4)   // 162816 B

template<int EPI>
__global__ void __launch_bounds__(512, 1)
gemm_mma(const float* __restrict__ A, const float* __restrict__ B,
         float* __restrict__ C, const float* __restrict__ bias,
         const float* __restrict__ resid, int M, int N, int K)
{
    extern __shared__ float sm[];
    float* AsAll = sm;                       // [TCS][256][36]
    float* BsAll = sm + TCS*A_STG;           // [TCS][32][136]
    const uint32_t sb = (uint32_t)__cvta_generic_to_shared(sm);

    const int tid = threadIdx.x;
    const int wid = tid >> 5, lane = tid & 31;
    const int g   = lane >> 2, tig = lane & 3;
    const int wm  = wid >> 2;                // 0..3 (64 rows each)
    const int wn  = wid & 3;                 // 0..3 (32 cols each)
    const int m0  = blockIdx.x * BM;
    const int n0  = blockIdx.y * BN;
    const int KT  = K >> 5;

    float acc[4][4][4];                      // [mf][nf][reg]
    #pragma unroll
    for (int i=0;i<4;i++)
        #pragma unroll
        for (int j=0;j<4;j++)
            #pragma unroll
            for (int t=0;t<4;t++) acc[i][j][t]=0.f;

    auto load_chunk = [&](int st, int kc){
        const int k0 = kc << 5;
        const uint32_t ab = sb + (uint32_t)(st*A_STG*4);
        const uint32_t bb = sb + (uint32_t)((TCS*A_STG + st*B_STG)*4);
        #pragma unroll
        for (int it=0; it<4; it++){                      // A: 256 rows x 8 float4 = 2048
            int qi = tid + it*512;
            int r  = qi >> 3, c4 = qi & 7;
            cp_async16_s(ab + (uint32_t)(r*144 + c4*16), A + (size_t)(m0+r)*K + k0 + c4*4);
        }
        #pragma unroll
        for (int it=0; it<2; it++){                      // B: 32 rows x 32 float4 = 1024
            int qi = tid + it*512;
            int rb = qi >> 5, cb = qi & 31;
            cp_async16_s(bb + (uint32_t)(rb*544 + cb*16), B + (size_t)(k0+rb)*N + n0 + cb*4);
        }
    };

    auto compute = [&](int st){
        const float* As = AsAll + st*A_STG;
        const float* Bs = BsAll + st*B_STG;
        #pragma unroll
        for (int ks=0; ks<32; ks+=8){
            uint32_t bfr[4][2];
            #pragma unroll
            for (int nf=0; nf<4; nf++){
                int col = wn*32 + nf*8 + g;
                bfr[nf][0] = rn_tf32_bits(Bs[(ks+tig  )*136 + col]);
                bfr[nf][1] = rn_tf32_bits(Bs[(ks+tig+4)*136 + col]);
            }
            #pragma unroll
            for (int mf=0; mf<4; mf++){
                int row = wm*64 + mf*16;
                uint32_t a0 = __float_as_uint(As[(row+g  )*36 + ks + tig  ]);
                uint32_t a1 = __float_as_uint(As[(row+g+8)*36 + ks + tig  ]);
                uint32_t a2 = __float_as_uint(As[(row+g  )*36 + ks + tig+4]);
                uint32_t a3 = __float_as_uint(As[(row+g+8)*36 + ks + tig+4]);
                #pragma unroll
                for (int nf=0; nf<4; nf++)
                    mma_tf32(acc[mf][nf], a0, a1, a2, a3, bfr[nf][0], bfr[nf][1]);
            }
        }
    };

    load_chunk(0, 0); cp_commit();
    load_chunk(1, 1); cp_commit();

    int st = 0;
    for (int kt=0; kt<KT; kt++){
        cp_wait<1>();
        __syncthreads();
        compute(st);
        int nc = kt + 2;
        if (nc < KT){
            int ns = st + 2; if (ns >= TCS) ns -= TCS;
            load_chunk(ns, nc);
        }
        cp_commit();
        st = (st+1 == TCS) ? 0 : st+1;
    }

    // epilogue
    #pragma unroll
    for (int mf=0; mf<4; mf++){
        int mrow = m0 + wm*64 + mf*16 + g;               // logical input row
        int r0 = (EPI==1) ? (((mrow>>7)<<8) + 128 + (mrow & 127)) : mrow;
        int r1 = (EPI==1) ? ((((mrow+8)>>7)<<8) + 128 + ((mrow+8) & 127)) : (mrow+8);
        #pragma unroll
        for (int nf=0; nf<4; nf++){
            int c0 = n0 + wn*32 + nf*8 + 2*tig;
            float2 v0 = make_float2(acc[mf][nf][0], acc[mf][nf][1]);
            float2 v1 = make_float2(acc[mf][nf][2], acc[mf][nf][3]);
            if (EPI==2){
                const float2 r0v = *(const float2*)(resid + (size_t)r0*N + c0);
                const float2 r1v = *(const float2*)(resid + (size_t)r1*N + c0);
                v0.x += r0v.x; v0.y += r0v.y; v1.x += r1v.x; v1.y += r1v.y;
            } else if (EPI==1){
                float b0 = bias[c0], b1 = bias[c0+1];
                v0.x += b0; v0.y += b1; v1.x += b0; v1.y += b1;
            }
            *(float2*)(C + (size_t)r0*N + c0) = v0;
            *(float2*)(C + (size_t)r1*N + c0) = v1;
        }
    }
}

// ---------------- embedding assembly ----------------
__global__ void gather_embed(const int* __restrict__ ids, const float* __restrict__ table,
                             float* __restrict__ h)
{
    int b = blockIdx.x >> 7, s = blockIdx.x & 127;
    int id = ids[b*SP + s];
    const float4* src = (const float4*)(table + (size_t)id*D_LLM);
    float4* dst = (float4*)(h + (size_t)(b*SEQ + s)*D_LLM);
    #pragma unroll
    for (int it=0; it<4; it++) dst[threadIdx.x + it*256] = src[threadIdx.x + it*256];
}

__global__ void stage_tv(const float* __restrict__ text, const float* __restrict__ vision,
                         float* __restrict__ tv)
{
    int b = blockIdx.x >> 7, r = blockIdx.x & 127;
    const float* src = (r < 64) ? (text + (size_t)(b*64 + r)*768)
                                : (vision + (size_t)(b*64 + (r-64))*768);
    float* dst = tv + (size_t)blockIdx.x*768;
    #pragma unroll
    for (int it=0; it<3; it++) dst[threadIdx.x + it*256] = rn_tf32(src[threadIdx.x + it*256]);
}

// ---------------- rmsnorm (RND: round output to tf32 for GEMM-A use) ----------------
template<bool RND>
__global__ void rmsnorm_kernel(const float* __restrict__ in, const float* __restrict__ w,
                               float* __restrict__ out)
{
    int row = blockIdx.x;
    const float* p = in + (size_t)row*D_LLM;
    float ss = 0.f;
    for (int d=threadIdx.x; d<D_LLM; d+=256){ float vv = p[d]; ss += vv*vv; }
    float tot = blockReduceSum(ss);
    float r = rsqrtf(tot*(1.0f/D_LLM) + EPSR);
    float* q = out + (size_t)row*D_LLM;
    for (int d=threadIdx.x; d<D_LLM; d+=256){
        float v = p[d]*r*w[d];
        q[d] = RND ? rn_tf32(v) : v;
    }
}

// ---------------- rope (in-place, q & k) ----------------
__global__ void rope_kernel(float* __restrict__ q, float* __restrict__ k)
{
    int m = blockIdx.x;
    int s = m & (SEQ-1);
    float* qr = q + (size_t)m*D_LLM;
    float* kr = k + (size_t)m*D_LLM;
    for (int p = threadIdx.x; p < NH*64; p += 256){
        int hh = p >> 6, i = p & 63;
        float invf = powf(10000.f, -(float)i * (1.f/64.f));
        float ang = (float)s * invf;
        float c, sn; sincosf(ang, &sn, &c);
        int b0 = hh*HD + i;
        float x1 = qr[b0], x2 = qr[b0+64];
        qr[b0]    = x1*c - x2*sn;
        qr[b0+64] = x2*c + x1*sn;
        x1 = kr[b0]; x2 = kr[b0+64];
        kr[b0]    = x1*c - x2*sn;
        kr[b0+64] = x2*c + x1*sn;
    }
}

// ---------------- attention: scores (Q K^T * scale), per (b,h), 64x64 tiles ----------------
__global__ void __launch_bounds__(256)
attn_scores(const float* __restrict__ Q, const float* __restrict__ K, float* __restrict__ att)
{
    int bh = blockIdx.z;
    int b = bh >> 5, h = bh & 31;
    int i0 = blockIdx.y*64, j0 = blockIdx.x*64;
    if (j0 > i0) return;

    __shared__ float Qs[64][33], Ks[64][33];
    int tid = threadIdx.x;
    int ty = tid >> 4, tx = tid & 15;
    float acc[4][4];
    #pragma unroll
    for (int r=0;r<4;r++)
        #pragma unroll
        for (int c=0;c<4;c++) acc[r][c]=0.f;

    const float* Qb = Q + (size_t)(b*SEQ + i0)*D_LLM + h*HD;
    const float* Kb = K + (size_t)(b*SEQ + j0)*D_LLM + h*HD;

    for (int d0=0; d0<HD; d0+=32){
        #pragma unroll
        for (int it=0; it<2; it++){
            int qi = tid + it*256;
            int r = qi >> 3, c = (qi & 7) << 2;
            float4 va = *(const float4*)(Qb + (size_t)r*D_LLM + d0 + c);
            Qs[r][c]=va.x; Qs[r][c+1]=va.y; Qs[r][c+2]=va.z; Qs[r][c+3]=va.w;
            float4 vb = *(const float4*)(Kb + (size_t)r*D_LLM + d0 + c);
            Ks[r][c]=vb.x; Ks[r][c+1]=vb.y; Ks[r][c+2]=vb.z; Ks[r][c+3]=vb.w;
        }
        __syncthreads();
        #pragma unroll
        for (int kk=0;kk<32;kk++){
            float a[4], bb[4];
            #pragma unroll
            for (int r=0;r<4;r++) a[r]=Qs[ty*4+r][kk];
            #pragma unroll
            for (int c=0;c<4;c++) bb[c]=Ks[tx*4+c][kk];
            #pragma unroll
            for (int r=0;r<4;r++)
                #pragma unroll
                for (int c=0;c<4;c++) acc[r][c] += a[r]*bb[c];
        }
        __syncthreads();
    }
    const float scale = 0.08838834764831845f;
    float* out = att + ((size_t)bh*SEQ + i0)*SEQ + j0;
    #pragma unroll
    for (int r=0;r<4;r++)
        #pragma unroll
        for (int c=0;c<4;c++)
            out[(size_t)(ty*4+r)*SEQ + tx*4+c] = acc[r][c]*scale;
}

// ---------------- softmax with causal mask ----------------
__global__ void softmax_kernel(float* __restrict__ att)
{
    int row = blockIdx.x;
    int i = row & (SEQ-1);
    int j = threadIdx.x;
    float* p = att + (size_t)row*SEQ;
    float v = (j <= i) ? p[j] : -3.0e38f;
    float mx = blockReduceMax(v);
    float e = (j <= i) ? __expf(v - mx) : 0.f;
    float s = blockReduceSum(e);
    p[j] = e / s;
}

// ---------------- attention: O = P V (rounded: A-input of Wo GEMM) ----------------
__global__ void __launch_bounds__(256)
attn_av(const float* __restrict__ att, const float* __restrict__ V, float* __restrict__ O)
{
    int bh = blockIdx.z;
    int b = bh >> 5, h = bh & 31;
    int i0 = blockIdx.y*64, d0 = blockIdx.x*64;

    __shared__ float Ps[64][33], Vs[32][65];
    int tid = threadIdx.x;
    int ty = tid >> 4, tx = tid & 15;
    float acc[4][4];
    #pragma unroll
    for (int r=0;r<4;r++)
        #pragma unroll
        for (int c=0;c<4;c++) acc[r][c]=0.f;

    const float* Pb = att + ((size_t)bh*SEQ + i0)*SEQ;
    const float* Vb = V + (size_t)(b*SEQ)*D_LLM + h*HD + d0;

    int jend = i0 + 64;
    for (int j0=0; j0<jend; j0+=32){
        #pragma unroll
        for (int it=0; it<2; it++){
            int qi = tid + it*256;
            int r = qi >> 3, c = (qi & 7) << 2;
            float4 va = *(const float4*)(Pb + (size_t)r*SEQ + j0 + c);
            Ps[r][c]=va.x; Ps[r][c+1]=va.y; Ps[r][c+2]=va.z; Ps[r][c+3]=va.w;
            int rv = qi >> 4, cv = (qi & 15) << 2;
            float4 vb = *(const float4*)(Vb + (size_t)(j0+rv)*D_LLM + cv);
            Vs[rv][cv]=vb.x; Vs[rv][cv+1]=vb.y; Vs[rv][cv+2]=vb.z; Vs[rv][cv+3]=vb.w;
        }
        __syncthreads();
        #pragma unroll
        for (int kk=0;kk<32;kk++){
            float a[4], bb[4];
            #pragma unroll
            for (int r=0;r<4;r++) a[r]=Ps[ty*4+r][kk];
            #pragma unroll
            for (int c=0;c<4;c++) bb[c]=Vs[kk][tx*4+c];
            #pragma unroll
            for (int r=0;r<4;r++)
                #pragma unroll
                for (int c=0;c<4;c++) acc[r][c] += a[r]*bb[c];
        }
        __syncthreads();
    }
    float* out = O + (size_t)(b*SEQ + i0)*D_LLM + h*HD + d0;
    #pragma unroll
    for (int r=0;r<4;r++)
        #pragma unroll
        for (int c=0;c<4;c++)
            out[(size_t)(ty*4+r)*D_LLM + tx*4+c] = rn_tf32(acc[r][c]);
}

// ---------------- silu(gate) * up -> gate (rounded: A-input of Wd GEMM) ----------------
__global__ void silu_mul(float* __restrict__ g, const float* __restrict__ u)
{
    size_t idx = (size_t)blockIdx.x*256 + threadIdx.x;
    float gv = g[idx];
    g[idx] = rn_tf32(gv / (1.f + __expf(-gv)) * u[idx]);
}

// ---------------- mean pool over sequence ----------------
__global__ void pool_kernel(const float* __restrict__ x, float* __restrict__ pool)
{
    int b = blockIdx.y;
    int d = blockIdx.x*256 + threadIdx.x;
    float acc = 0.f;
    const float* p = x + (size_t)(b*SEQ)*D_LLM + d;
    for (int s=0; s<SEQ; s++) acc += p[(size_t)s*D_LLM];
    pool[b*D_LLM + d] = acc * (1.f/SEQ);
}

// ---------------- head ----------------
__global__ void head1_kernel(const float* __restrict__ pool, const float* __restrict__ W1,
                             const float* __restrict__ b1, float* __restrict__ y1)
{
    __shared__ float sp[D_LLM];
    int b = blockIdx.y;
    for (int kk=threadIdx.x; kk<D_LLM; kk+=256) sp[kk]=pool[b*D_LLM+kk];
    __syncthreads();
    int n = blockIdx.x*256 + threadIdx.x;
    float acc = b1[n];
    for (int kk=0; kk<D_LLM; kk++) acc += sp[kk]*W1[(size_t)kk*768 + n];
    y1[b*768 + n] = acc;
}

__global__ void head2_kernel(const float* __restrict__ y1, const float* __restrict__ W2,
                             const float* __restrict__ b2, float* __restrict__ out)
{
    int b = blockIdx.x;
    float acc = 0.f;
    for (int kk=threadIdx.x; kk<768; kk+=256) acc += y1[b*768+kk]*W2[kk];
    float tot = blockReduceSum(acc);
    if (threadIdx.x==0) out[b] = tot + b2[0];
}

// ---------------- host orchestration ----------------
extern "C" void kernel_launch(void* const* d_in, const int* in_sizes, int n_in,
                              void* d_out, int out_size)
{
    const float* text   = (const float*)d_in[0];
    const float* vision = (const float*)d_in[1];
    const int*   ids    = (const int*)  d_in[2];
    const float* in_W   = (const float*)d_in[3];
    const float* in_b   = (const float*)d_in[4];
    const float* table  = (const float*)d_in[5];
    const float* Wq     = (const float*)d_in[6];
    const float* Wk     = (const float*)d_in[7];
    const float* Wv     = (const float*)d_in[8];
    const float* Wo     = (const float*)d_in[9];
    const float* ln1    = (const float*)d_in[10];
    const float* ln2    = (const float*)d_in[11];
    const float* Wg     = (const float*)d_in[12];
    const float* Wu     = (const float*)d_in[13];
    const float* Wd     = (const float*)d_in[14];
    const float* fnw    = (const float*)d_in[15];
    const float* o1W    = (const float*)d_in[16];
    const float* o1b    = (const float*)d_in[17];
    const float* o2W    = (const float*)d_in[18];
    const float* o2b    = (const float*)d_in[19];
    float* out = (float*)d_out;

    float *h,*x,*q,*k,*v,*o,*att,*gate,*up,*tv,*pool,*y1;
    cudaGetSymbolAddress((void**)&h,    g_h);
    cudaGetSymbolAddress((void**)&x,    g_x);
    cudaGetSymbolAddress((void**)&q,    g_q);
    cudaGetSymbolAddress((void**)&k,    g_k);
    cudaGetSymbolAddress((void**)&v,    g_v);
    cudaGetSymbolAddress((void**)&o,    g_o);
    cudaGetSymbolAddress((void**)&att,  g_att);
    cudaGetSymbolAddress((void**)&gate, g_gate);
    cudaGetSymbolAddress((void**)&up,   g_up);
    cudaGetSymbolAddress((void**)&tv,   g_tv);
    cudaGetSymbolAddress((void**)&pool, g_pool);
    cudaGetSymbolAddress((void**)&y1,   g_y1);

    cudaFuncSetAttribute(gemm_mma<0>, cudaFuncAttributeMaxDynamicSharedMemorySize, TC_SMEM);
    cudaFuncSetAttribute(gemm_mma<1>, cudaFuncAttributeMaxDynamicSharedMemorySize, TC_SMEM);
    cudaFuncSetAttribute(gemm_mma<2>, cudaFuncAttributeMaxDynamicSharedMemorySize, TC_SMEM);

    // --- embedding assembly
    gather_embed<<<NB*SP, 256>>>(ids, table, h);
    stage_tv<<<MTV, 256>>>(text, vision, tv);
    gemm_mma<1><<<dim3(MTV/BM, D_LLM/BN), 512, TC_SMEM>>>(tv, in_W, h, in_b, nullptr, MTV, D_LLM, 768);

    for (int l=0; l<2; l++){
        const float* wq = Wq + (size_t)l*D_LLM*D_LLM;
        const float* wk = Wk + (size_t)l*D_LLM*D_LLM;
        const float* wv = Wv + (size_t)l*D_LLM*D_LLM;
        const float* wo = Wo + (size_t)l*D_LLM*D_LLM;
        const float* wg = Wg + (size_t)l*D_LLM*D_FF;
        const float* wu = Wu + (size_t)l*D_LLM*D_FF;
        const float* wd = Wd + (size_t)l*D_FF*D_LLM;
        const float* l1 = ln1 + (size_t)l*D_LLM;
        const float* l2 = ln2 + (size_t)l*D_LLM;

        rmsnorm_kernel<true><<<MROWS, 256>>>(h, l1, x);
        gemm_mma<0><<<dim3(MROWS/BM, D_LLM/BN), 512, TC_SMEM>>>(x, wq, q, nullptr, nullptr, MROWS, D_LLM, D_LLM);
        gemm_mma<0><<<dim3(MROWS/BM, D_LLM/BN), 512, TC_SMEM>>>(x, wk, k, nullptr, nullptr, MROWS, D_LLM, D_LLM);
        gemm_mma<0><<<dim3(MROWS/BM, D_LLM/BN), 512, TC_SMEM>>>(x, wv, v, nullptr, nullptr, MROWS, D_LLM, D_LLM);
        rope_kernel<<<MROWS, 256>>>(q, k);
        attn_scores<<<dim3(SEQ/64, SEQ/64, NB*NH), 256>>>(q, k, att);
        softmax_kernel<<<NB*NH*SEQ, 256>>>(att);
        attn_av<<<dim3(HD/64, SEQ/64, NB*NH), 256>>>(att, v, o);
        gemm_mma<2><<<dim3(MROWS/BM, D_LLM/BN), 512, TC_SMEM>>>(o, wo, h, nullptr, h, MROWS, D_LLM, D_LLM);

        rmsnorm_kernel<true><<<MROWS, 256>>>(h, l2, x);
        gemm_mma<0><<<dim3(MROWS/BM, D_FF/BN), 512, TC_SMEM>>>(x, wg, gate, nullptr, nullptr, MROWS, D_FF, D_LLM);
        gemm_mma<0><<<dim3(MROWS/BM, D_FF/BN), 512, TC_SMEM>>>(x, wu, up,   nullptr, nullptr, MROWS, D_FF, D_LLM);
        silu_mul<<<(MROWS*(size_t)D_FF)/256, 256>>>(gate, up);
        gemm_mma<2><<<dim3(MROWS/BM, D_LLM/BN), 512, TC_SMEM>>>(gate, wd, h, nullptr, h, MROWS, D_LLM, D_FF);
    }

    rmsnorm_kernel<false><<<MROWS, 256>>>(h, fnw, x);
    pool_kernel<<<dim3(D_LLM/256, NB), 256>>>(x, pool);
    head1_kernel<<<dim3(768/256, NB), 256>>>(pool, o1W, o1b, y1);
    head2_kernel<<<NB, 256>>>(y1, o2W, o2b, out);
}